// round 1
// baseline (speedup 1.0000x reference)
#include <cuda_runtime.h>
#include <cstdint>

#define SEQ   256
#define NB    64
#define INP   1024
#define HID   1024
#define NG    4096   // 4*HID
#define SBH   (SEQ*NB*HID)

// ---- device scratch (no allocations allowed) ----
__device__ float g_xm[(size_t)SEQ*NB*INP];   // x * mask_x        (64 MB)
__device__ float g_xg[(size_t)SEQ*NB*NG];    // input gate proj   (256 MB)
__device__ float g_hm[2][NB*HID];            // masked h, ping-pong
__device__ float g_c[NB*HID];                // cell state

__device__ __forceinline__ uint32_t f2tf(float f) {
    uint32_t u;
    asm("cvt.rna.tf32.f32 %0, %1;" : "=r"(u) : "f"(f));
    return u;
}
__device__ __forceinline__ void mma8(float* d, const uint32_t* a, const uint32_t* b) {
    asm volatile(
        "mma.sync.aligned.m16n8k8.row.col.f32.tf32.tf32.f32 "
        "{%0,%1,%2,%3},{%4,%5,%6,%7},{%8,%9},{%0,%1,%2,%3};\n"
        : "+f"(d[0]), "+f"(d[1]), "+f"(d[2]), "+f"(d[3])
        : "r"(a[0]), "r"(a[1]), "r"(a[2]), "r"(a[3]), "r"(b[0]), "r"(b[1]));
}
__device__ __forceinline__ float sigf(float x)  { return 1.f/(1.f+__expf(-x)); }
__device__ __forceinline__ float tanh_f(float x){ return 2.f/(1.f+__expf(-2.f*x)) - 1.f; }

// ---- x * mask_x (mask broadcast over SEQ; B*IN = 65536 = 2^16) ----
__global__ void k_maskx(const float* __restrict__ x, const float* __restrict__ mx) {
    size_t i = ((size_t)blockIdx.x*256 + threadIdx.x)*4;
    float4 v = *reinterpret_cast<const float4*>(x + i);
    float4 m = *reinterpret_cast<const float4*>(mx + (i & 65535));
    v.x*=m.x; v.y*=m.y; v.z*=m.z; v.w*=m.w;
    *reinterpret_cast<float4*>(g_xm + i) = v;
}

// ---- init: hm0 = h0*mask_h, c = c0 ----
__global__ void k_setup(const float* __restrict__ h0, const float* __restrict__ c0,
                        const float* __restrict__ mh) {
    int i = blockIdx.x*256 + threadIdx.x;
    g_hm[0][i] = h0[i]*mh[i];
    g_c[i]     = c0[i];
}

// ---- input projection: g_xg[m][n] = g_xm[m][:] . W_ih[n][:] + b_ih[n] + b_hh[n]
// CTA tile 128x128, K-chunk 32, tf32 mma, 8 warps (warp tile 64x32)
__global__ void __launch_bounds__(256) k_gemm_x(const float* __restrict__ W,
                                                const float* __restrict__ b_ih,
                                                const float* __restrict__ b_hh) {
    __shared__ uint32_t sA[128*36];
    __shared__ uint32_t sB[128*36];
    const int tid  = threadIdx.x;
    const int lane = tid & 31;
    const int w    = tid >> 5;
    const int wm   = (w & 1) * 64;
    const int wn   = (w >> 1) * 32;
    const int m0   = blockIdx.y * 128;
    const int n0   = blockIdx.x * 128;

    const int rbase = tid >> 3;   // 0..31
    const int kq    = tid & 7;    // float4 column within 32-wide chunk

    float acc[4][4][4];
    #pragma unroll
    for (int i = 0; i < 4; i++)
        #pragma unroll
        for (int j = 0; j < 4; j++)
            #pragma unroll
            for (int e = 0; e < 4; e++) acc[i][j][e] = 0.f;

    float4 a4[4], b4[4];
    // prefetch chunk 0
    {
        const int col = kq*4;
        #pragma unroll
        for (int r = 0; r < 4; r++) {
            const int row = rbase + 32*r;
            a4[r] = *reinterpret_cast<const float4*>(g_xm + (size_t)(m0+row)*INP + col);
            b4[r] = *reinterpret_cast<const float4*>(W    + (size_t)(n0+row)*INP + col);
        }
    }

    for (int kc = 0; kc < 32; ++kc) {
        __syncthreads();
        #pragma unroll
        for (int r = 0; r < 4; r++) {
            const int row = rbase + 32*r;
            const float* av = reinterpret_cast<const float*>(&a4[r]);
            const float* bv = reinterpret_cast<const float*>(&b4[r]);
            #pragma unroll
            for (int e = 0; e < 4; e++) {
                sA[row*36 + kq*4 + e] = f2tf(av[e]);
                sB[row*36 + kq*4 + e] = f2tf(bv[e]);
            }
        }
        __syncthreads();
        if (kc + 1 < 32) {
            const int col = (kc+1)*32 + kq*4;
            #pragma unroll
            for (int r = 0; r < 4; r++) {
                const int row = rbase + 32*r;
                a4[r] = *reinterpret_cast<const float4*>(g_xm + (size_t)(m0+row)*INP + col);
                b4[r] = *reinterpret_cast<const float4*>(W    + (size_t)(n0+row)*INP + col);
            }
        }
        #pragma unroll
        for (int kk = 0; kk < 4; ++kk) {
            uint32_t af[4][4];
            #pragma unroll
            for (int mt = 0; mt < 4; mt++) {
                const int r = wm + mt*16 + (lane>>2);
                const int c = kk*8 + (lane&3);
                af[mt][0] = sA[r*36 + c];
                af[mt][1] = sA[(r+8)*36 + c];
                af[mt][2] = sA[r*36 + c + 4];
                af[mt][3] = sA[(r+8)*36 + c + 4];
            }
            #pragma unroll
            for (int nt = 0; nt < 4; nt++) {
                const int rn = wn + nt*8 + (lane>>2);
                uint32_t bf[2];
                bf[0] = sB[rn*36 + kk*8 + (lane&3)];
                bf[1] = sB[rn*36 + kk*8 + (lane&3) + 4];
                #pragma unroll
                for (int mt = 0; mt < 4; mt++) mma8(acc[mt][nt], af[mt], bf);
            }
        }
    }

    // epilogue: + (b_ih + b_hh), write to g_xg
    #pragma unroll
    for (int mt = 0; mt < 4; mt++) {
        #pragma unroll
        for (int nt = 0; nt < 4; nt++) {
            const int gr = m0 + wm + mt*16 + (lane>>2);
            const int gc = n0 + wn + nt*8 + (lane&3)*2;
            const float bb0 = b_ih[gc]   + b_hh[gc];
            const float bb1 = b_ih[gc+1] + b_hh[gc+1];
            float* o = g_xg + (size_t)gr*NG + gc;
            o[0] = acc[mt][nt][0] + bb0;
            o[1] = acc[mt][nt][1] + bb1;
            o += (size_t)8*NG;
            o[0] = acc[mt][nt][2] + bb0;
            o[1] = acc[mt][nt][3] + bb1;
        }
    }
}

// ---- one recurrence step ----
// CTA cb owns hidden units j in [16*cb, 16*cb+16), all 4 gates (64 W rows), all 64 batch rows.
// gates[64 x 64] = hm[64 x 1024] @ Wsel^T, then LSTM cell fused in epilogue.
__global__ void __launch_bounds__(256) k_step(const float* __restrict__ Whh,
                                              const float* __restrict__ mh,
                                              float* __restrict__ out, int t) {
    __shared__ uint32_t sbuf[2*64*36];       // A tile | W tile; reused as gate buffer
    uint32_t* sA = sbuf;
    uint32_t* sW = sbuf + 64*36;

    const float* hm  = g_hm[t & 1];
    float*       hmn = g_hm[(t + 1) & 1];
    const int cb   = blockIdx.x;             // 0..63
    const int tid  = threadIdx.x;
    const int lane = tid & 31;
    const int w    = tid >> 5;
    const int mg   = (w & 3) * 16;
    const int nh   = (w >> 2) * 32;

    const int r0 = tid >> 3;                 // rows r0, r0+32
    const int kq = tid & 7;

    // W row mapping: tile col c -> gate g=c>>4, local j=c&15 -> global row g*1024 + cb*16 + j
    const int wr0 = ((r0 >> 4) * HID) + cb*16 + (r0 & 15);
    const int r1  = r0 + 32;
    const int wr1 = ((r1 >> 4) * HID) + cb*16 + (r1 & 15);

    const float* pA0 = hm  + (size_t)r0 * HID + kq*4;
    const float* pA1 = hm  + (size_t)r1 * HID + kq*4;
    const float* pW0 = Whh + (size_t)wr0 * HID + kq*4;
    const float* pW1 = Whh + (size_t)wr1 * HID + kq*4;

    float acc[4][4];
    #pragma unroll
    for (int i = 0; i < 4; i++)
        #pragma unroll
        for (int e = 0; e < 4; e++) acc[i][e] = 0.f;

    float4 a0 = *reinterpret_cast<const float4*>(pA0);
    float4 a1 = *reinterpret_cast<const float4*>(pA1);
    float4 w0 = *reinterpret_cast<const float4*>(pW0);
    float4 w1 = *reinterpret_cast<const float4*>(pW1);

    for (int kc = 0; kc < 32; ++kc) {
        __syncthreads();
        {
            const float* v;
            v = reinterpret_cast<const float*>(&a0);
            #pragma unroll
            for (int e = 0; e < 4; e++) sA[r0*36 + kq*4 + e] = f2tf(v[e]);
            v = reinterpret_cast<const float*>(&a1);
            #pragma unroll
            for (int e = 0; e < 4; e++) sA[r1*36 + kq*4 + e] = f2tf(v[e]);
            v = reinterpret_cast<const float*>(&w0);
            #pragma unroll
            for (int e = 0; e < 4; e++) sW[r0*36 + kq*4 + e] = f2tf(v[e]);
            v = reinterpret_cast<const float*>(&w1);
            #pragma unroll
            for (int e = 0; e < 4; e++) sW[r1*36 + kq*4 + e] = f2tf(v[e]);
        }
        __syncthreads();
        if (kc + 1 < 32) {
            const int off = (kc+1)*32;
            a0 = *reinterpret_cast<const float4*>(pA0 + off);
            a1 = *reinterpret_cast<const float4*>(pA1 + off);
            w0 = *reinterpret_cast<const float4*>(pW0 + off);
            w1 = *reinterpret_cast<const float4*>(pW1 + off);
        }
        #pragma unroll
        for (int kk = 0; kk < 4; ++kk) {
            uint32_t af[4];
            const int r = mg + (lane>>2);
            const int c = kk*8 + (lane&3);
            af[0] = sA[r*36 + c];
            af[1] = sA[(r+8)*36 + c];
            af[2] = sA[r*36 + c + 4];
            af[3] = sA[(r+8)*36 + c + 4];
            #pragma unroll
            for (int nt = 0; nt < 4; nt++) {
                const int rn = nh + nt*8 + (lane>>2);
                uint32_t bf[2];
                bf[0] = sW[rn*36 + kk*8 + (lane&3)];
                bf[1] = sW[rn*36 + kk*8 + (lane&3) + 4];
                mma8(acc[nt], af, bf);
            }
        }
    }

    // stage gates to SMEM (stride 68), then fused LSTM cell
    __syncthreads();
    float* gsm = reinterpret_cast<float*>(sbuf);
    #pragma unroll
    for (int nt = 0; nt < 4; nt++) {
        const int rr  = mg + (lane>>2);
        const int col = nh + nt*8 + (lane&3)*2;
        gsm[rr*68 + col]       = acc[nt][0];
        gsm[rr*68 + col + 1]   = acc[nt][1];
        gsm[(rr+8)*68 + col]   = acc[nt][2];
        gsm[(rr+8)*68 + col+1] = acc[nt][3];
    }
    __syncthreads();

    const int jl = tid & 15;
    const int b0 = tid >> 4;
    const int j  = cb*16 + jl;
    #pragma unroll
    for (int it = 0; it < 4; it++) {
        const int b = b0 + it*16;
        const float* xgp = g_xg + ((size_t)t*NB + b)*NG;
        float gi = gsm[b*68 + jl]      + xgp[j];
        float gf = gsm[b*68 + 16 + jl] + xgp[HID + j];
        float gg = gsm[b*68 + 32 + jl] + xgp[2*HID + j];
        float go = gsm[b*68 + 48 + jl] + xgp[3*HID + j];
        const float ig = sigf(gi);
        const float fg = sigf(gf);
        const float gv = tanh_f(gg);
        const float og = sigf(go);
        const int  idx = b*HID + j;
        const float cn = fg * g_c[idx] + ig * gv;
        g_c[idx] = cn;
        const float hn = og * tanh_f(cn);
        out[((size_t)t*NB + b)*HID + j] = hn;
        hmn[idx] = hn * mh[idx];
        if (t == SEQ - 1) {
            out[SBH + idx]            = hn;   // h_n
            out[SBH + NB*HID + idx]   = cn;   // c_n
        }
    }
}

extern "C" void kernel_launch(void* const* d_in, const int* in_sizes, int n_in,
                              void* d_out, int out_size) {
    const float* x      = (const float*)d_in[0];
    const float* h0     = (const float*)d_in[1];
    const float* c0     = (const float*)d_in[2];
    const float* mask_x = (const float*)d_in[3];
    const float* mask_h = (const float*)d_in[4];
    const float* W_ih   = (const float*)d_in[5];
    const float* W_hh   = (const float*)d_in[6];
    const float* b_ih   = (const float*)d_in[7];
    const float* b_hh   = (const float*)d_in[8];
    float* out = (float*)d_out;

    k_maskx<<<(SEQ*NB*INP)/(256*4), 256>>>(x, mask_x);
    k_setup<<<(NB*HID)/256, 256>>>(h0, c0, mask_h);
    k_gemm_x<<<dim3(NG/128, (SEQ*NB)/128), 256>>>(W_ih, b_ih, b_hh);
    for (int t = 0; t < SEQ; ++t)
        k_step<<<64, 256>>>(W_hh, mask_h, out, t);
    (void)in_sizes; (void)n_in; (void)out_size;
}

// round 3
// speedup vs baseline: 1.2178x; 1.2178x over previous
#include <cuda_runtime.h>
#include <cstdint>

#define SEQ   256
#define NB    64
#define INP   1024
#define HID   1024
#define NG    4096   // 4*HID
#define SBH   (SEQ*NB*HID)
#define NCTA  128
#define WSTR  1032   // W smem row stride (words)
#define ASTR  68     // A smem row stride (words)
#define ATILE (64*ASTR)

// ---- device scratch ----
__device__ float    g_xm[(size_t)SEQ*NB*INP];   // x * mask_x
__device__ float    g_xg[(size_t)SEQ*NB*NG];    // input gate projections
__device__ uint32_t g_hm[2][NB*HID];            // masked h (tf32 bits), ping-pong
__device__ uint32_t g_wt[(size_t)NCTA*32*HID];  // per-CTA W_hh tiles (tf32 bits)
__device__ int      g_bar[SEQ];                 // grid barrier counters

__device__ __forceinline__ uint32_t f2tf(float f) {
    uint32_t u;
    asm("cvt.rna.tf32.f32 %0, %1;" : "=r"(u) : "f"(f));
    return u;
}
__device__ __forceinline__ void mma8(float* d, const uint32_t* a, const uint32_t* b) {
    asm volatile(
        "mma.sync.aligned.m16n8k8.row.col.f32.tf32.tf32.f32 "
        "{%0,%1,%2,%3},{%4,%5,%6,%7},{%8,%9},{%0,%1,%2,%3};\n"
        : "+f"(d[0]), "+f"(d[1]), "+f"(d[2]), "+f"(d[3])
        : "r"(a[0]), "r"(a[1]), "r"(a[2]), "r"(a[3]), "r"(b[0]), "r"(b[1]));
}
__device__ __forceinline__ float sigf(float x)  { return 1.f/(1.f+__expf(-x)); }
__device__ __forceinline__ float tanh_f(float x){ return 2.f/(1.f+__expf(-2.f*x)) - 1.f; }
__device__ __forceinline__ void bar_red_release(int* p) {
    asm volatile("red.release.gpu.global.add.s32 [%0], 1;" :: "l"(p) : "memory");
}
__device__ __forceinline__ int bar_ld_acquire(int* p) {
    int v;
    asm volatile("ld.acquire.gpu.global.b32 %0, [%1];" : "=r"(v) : "l"(p) : "memory");
    return v;
}

// ---- x * mask_x ----
__global__ void k_maskx(const float* __restrict__ x, const float* __restrict__ mx) {
    size_t i = ((size_t)blockIdx.x*256 + threadIdx.x)*4;
    float4 v = *reinterpret_cast<const float4*>(x + i);
    float4 m = *reinterpret_cast<const float4*>(mx + (i & 65535));
    v.x*=m.x; v.y*=m.y; v.z*=m.z; v.w*=m.w;
    *reinterpret_cast<float4*>(g_xm + i) = v;
}

// ---- init: hm0 = tf32(h0*mask_h); zero barrier counters ----
__global__ void k_setup(const float* __restrict__ h0, const float* __restrict__ mh) {
    int i = blockIdx.x*256 + threadIdx.x;
    g_hm[0][i] = f2tf(h0[i]*mh[i]);
    if (blockIdx.x == 0) g_bar[threadIdx.x] = 0;
}

// ---- W_hh prep: per-CTA tiles, tf32, row-major [cb][n][k], n = g*8 + j ----
__global__ void k_wprep(const float* __restrict__ W) {
    int base = (blockIdx.x*256 + threadIdx.x)*4;
    #pragma unroll
    for (int e = 0; e < 4; e++) {
        int dd = base + e;
        int cb = dd >> 15;
        int n  = (dd >> 10) & 31;
        int k  = dd & 1023;
        int g = n >> 3, j = n & 7;
        g_wt[dd] = f2tf(W[((size_t)(g*HID + cb*8 + j))*HID + k]);
    }
}

// ---- input projection GEMM (unchanged from R1, passed) ----
__global__ void __launch_bounds__(256) k_gemm_x(const float* __restrict__ W,
                                                const float* __restrict__ b_ih,
                                                const float* __restrict__ b_hh) {
    __shared__ uint32_t sA[128*36];
    __shared__ uint32_t sB[128*36];
    const int tid  = threadIdx.x;
    const int lane = tid & 31;
    const int w    = tid >> 5;
    const int wm   = (w & 1) * 64;
    const int wn   = (w >> 1) * 32;
    const int m0   = blockIdx.y * 128;
    const int n0   = blockIdx.x * 128;

    const int rbase = tid >> 3;
    const int kq    = tid & 7;

    float acc[4][4][4];
    #pragma unroll
    for (int i = 0; i < 4; i++)
        #pragma unroll
        for (int j = 0; j < 4; j++)
            #pragma unroll
            for (int e = 0; e < 4; e++) acc[i][j][e] = 0.f;

    float4 a4[4], b4[4];
    {
        const int col = kq*4;
        #pragma unroll
        for (int r = 0; r < 4; r++) {
            const int row = rbase + 32*r;
            a4[r] = *reinterpret_cast<const float4*>(g_xm + (size_t)(m0+row)*INP + col);
            b4[r] = *reinterpret_cast<const float4*>(W    + (size_t)(n0+row)*INP + col);
        }
    }

    for (int kc = 0; kc < 32; ++kc) {
        __syncthreads();
        #pragma unroll
        for (int r = 0; r < 4; r++) {
            const int row = rbase + 32*r;
            const float* av = reinterpret_cast<const float*>(&a4[r]);
            const float* bv = reinterpret_cast<const float*>(&b4[r]);
            #pragma unroll
            for (int e = 0; e < 4; e++) {
                sA[row*36 + kq*4 + e] = f2tf(av[e]);
                sB[row*36 + kq*4 + e] = f2tf(bv[e]);
            }
        }
        __syncthreads();
        if (kc + 1 < 32) {
            const int col = (kc+1)*32 + kq*4;
            #pragma unroll
            for (int r = 0; r < 4; r++) {
                const int row = rbase + 32*r;
                a4[r] = *reinterpret_cast<const float4*>(g_xm + (size_t)(m0+row)*INP + col);
                b4[r] = *reinterpret_cast<const float4*>(W    + (size_t)(n0+row)*INP + col);
            }
        }
        #pragma unroll
        for (int kk = 0; kk < 4; ++kk) {
            uint32_t af[4][4];
            #pragma unroll
            for (int mt = 0; mt < 4; mt++) {
                const int r = wm + mt*16 + (lane>>2);
                const int c = kk*8 + (lane&3);
                af[mt][0] = sA[r*36 + c];
                af[mt][1] = sA[(r+8)*36 + c];
                af[mt][2] = sA[r*36 + c + 4];
                af[mt][3] = sA[(r+8)*36 + c + 4];
            }
            #pragma unroll
            for (int nt = 0; nt < 4; nt++) {
                const int rn = wn + nt*8 + (lane>>2);
                uint32_t bf[2];
                bf[0] = sB[rn*36 + kk*8 + (lane&3)];
                bf[1] = sB[rn*36 + kk*8 + (lane&3) + 4];
                #pragma unroll
                for (int mt = 0; mt < 4; mt++) mma8(acc[mt][nt], af[mt], bf);
            }
        }
    }

    #pragma unroll
    for (int mt = 0; mt < 4; mt++) {
        #pragma unroll
        for (int nt = 0; nt < 4; nt++) {
            const int gr = m0 + wm + mt*16 + (lane>>2);
            const int gc = n0 + wn + nt*8 + (lane&3)*2;
            const float bb0 = b_ih[gc]   + b_hh[gc];
            const float bb1 = b_ih[gc+1] + b_hh[gc+1];
            float* o = g_xg + (size_t)gr*NG + gc;
            o[0] = acc[mt][nt][0] + bb0;
            o[1] = acc[mt][nt][1] + bb1;
            o += (size_t)8*NG;
            o[0] = acc[mt][nt][2] + bb0;
            o[1] = acc[mt][nt][3] + bb1;
        }
    }
}

// ---- persistent recurrence kernel ----
// 128 CTAs; CTA cb owns 8 hidden units (cb*8..cb*8+7) x 4 gates (32 W rows).
// W tile resident in SMEM for all 256 steps; c state in registers.
// h loads via __ldcg (L2); grid barrier = CG-style release/acquire.
__global__ void __launch_bounds__(256, 1) k_rnn(const float* __restrict__ c0,
                                                const float* __restrict__ mh,
                                                float* __restrict__ out) {
    extern __shared__ uint32_t sm[];
    uint32_t* sW  = sm;                          // 32 * 1032
    uint32_t* sA  = sm + 32*WSTR;                // 2 * 64*68
    float*    gsm = (float*)(sm + 32*WSTR + 2*ATILE);  // 64*36 (dedicated)

    const int cb   = blockIdx.x;
    const int tid  = threadIdx.x;
    const int lane = tid & 31;
    const int w    = tid >> 5;
    const int wm   = (w & 3) * 16;               // batch offset of warp
    const int wn   = (w >> 2) * 16;              // gate-col offset of warp
    const int lq   = lane >> 2;
    const int q4   = lane & 3;

    // preload W tile into SMEM (once)
    {
        const uint4* wsrc = reinterpret_cast<const uint4*>(g_wt + (size_t)cb*32768);
        #pragma unroll
        for (int i = 0; i < 32; i++) {
            int idx = tid + i*256;               // float4 index, 256 per row
            int row = idx >> 8, c4 = idx & 255;
            uint4 v = __ldcg(wsrc + idx);
            *reinterpret_cast<uint4*>(&sW[row*WSTR + c4*4]) = v;
        }
    }

    // per-thread cell state: 2 (batch, unit) elements
    float c_r[2], mh_r[2];
    int   bj[2];
    #pragma unroll
    for (int i = 0; i < 2; i++) {
        int e = tid + i*256;
        int b = e >> 3, j = e & 7;
        int gidx = b*HID + cb*8 + j;
        bj[i]   = gidx;
        c_r[i]  = c0[gidx];
        mh_r[i] = mh[gidx];
    }
    __syncthreads();

    const int arow = tid >> 2;                   // batch row this thread loads
    const int aq   = tid & 3;                    // quarter of the 64-wide chunk

    for (int t = 0; t < SEQ; ++t) {
        const uint32_t* hmc = g_hm[t & 1];
        uint32_t*       hmn = g_hm[(t + 1) & 1];
        const float*    xgt = g_xg + (size_t)t*NB*NG;

        // prefetch this step's xg slice (hidden under the GEMM)
        float xr[2][4];
        #pragma unroll
        for (int i = 0; i < 2; i++) {
            int e = tid + i*256;
            int b = e >> 3, j = e & 7;
            #pragma unroll
            for (int g = 0; g < 4; g++)
                xr[i][g] = __ldg(xgt + (size_t)b*NG + g*HID + cb*8 + j);
        }

        float acc[2][4];
        #pragma unroll
        for (int nt = 0; nt < 2; nt++)
            #pragma unroll
            for (int e = 0; e < 4; e++) acc[nt][e] = 0.f;

        // 2-deep register prefetch of h chunks (L2 loads)
        const uint4* abase = reinterpret_cast<const uint4*>(hmc + (size_t)arow*HID);
        uint4 rA[4], rB[4];
        #pragma unroll
        for (int i = 0; i < 4; i++) rA[i] = __ldcg(abase + 0*16 + aq*4 + i);
        #pragma unroll
        for (int i = 0; i < 4; i++) rB[i] = __ldcg(abase + 1*16 + aq*4 + i);

        #pragma unroll 1
        for (int ch = 0; ch < 16; ch += 2) {
            // ---- even chunk: data in rA, buffer 0 ----
            #pragma unroll
            for (int i = 0; i < 4; i++)
                *reinterpret_cast<uint4*>(&sA[0*ATILE + arow*ASTR + aq*16 + i*4]) = rA[i];
            __syncthreads();
            if (ch + 2 < 16) {
                #pragma unroll
                for (int i = 0; i < 4; i++) rA[i] = __ldcg(abase + (ch+2)*16 + aq*4 + i);
            }
            #pragma unroll
            for (int kk = 0; kk < 8; kk++) {
                uint32_t af[4];
                af[0] = sA[0*ATILE + (wm+lq)*ASTR   + kk*8 + q4];
                af[1] = sA[0*ATILE + (wm+lq+8)*ASTR + kk*8 + q4];
                af[2] = sA[0*ATILE + (wm+lq)*ASTR   + kk*8 + q4 + 4];
                af[3] = sA[0*ATILE + (wm+lq+8)*ASTR + kk*8 + q4 + 4];
                #pragma unroll
                for (int nt = 0; nt < 2; nt++) {
                    uint32_t bf[2];
                    const int rn = (wn + nt*8 + lq)*WSTR + ch*64 + kk*8 + q4;
                    bf[0] = sW[rn];
                    bf[1] = sW[rn + 4];
                    mma8(acc[nt], af, bf);
                }
            }
            // ---- odd chunk: data in rB, buffer 1 ----
            #pragma unroll
            for (int i = 0; i < 4; i++)
                *reinterpret_cast<uint4*>(&sA[1*ATILE + arow*ASTR + aq*16 + i*4]) = rB[i];
            __syncthreads();
            if (ch + 3 < 16) {
                #pragma unroll
                for (int i = 0; i < 4; i++) rB[i] = __ldcg(abase + (ch+3)*16 + aq*4 + i);
            }
            #pragma unroll
            for (int kk = 0; kk < 8; kk++) {
                uint32_t af[4];
                af[0] = sA[1*ATILE + (wm+lq)*ASTR   + kk*8 + q4];
                af[1] = sA[1*ATILE + (wm+lq+8)*ASTR + kk*8 + q4];
                af[2] = sA[1*ATILE + (wm+lq)*ASTR   + kk*8 + q4 + 4];
                af[3] = sA[1*ATILE + (wm+lq+8)*ASTR + kk*8 + q4 + 4];
                #pragma unroll
                for (int nt = 0; nt < 2; nt++) {
                    uint32_t bf[2];
                    const int rn = (wn + nt*8 + lq)*WSTR + (ch+1)*64 + kk*8 + q4;
                    bf[0] = sW[rn];
                    bf[1] = sW[rn + 4];
                    mma8(acc[nt], af, bf);
                }
            }
        }

        // stage gates to dedicated SMEM region, then fused LSTM cell
        #pragma unroll
        for (int nt = 0; nt < 2; nt++) {
            int rr = wm + lq, col = wn + nt*8 + q4*2;
            gsm[rr*36 + col]       = acc[nt][0];
            gsm[rr*36 + col + 1]   = acc[nt][1];
            gsm[(rr+8)*36 + col]   = acc[nt][2];
            gsm[(rr+8)*36 + col+1] = acc[nt][3];
        }
        __syncthreads();

        #pragma unroll
        for (int i = 0; i < 2; i++) {
            int e = tid + i*256;
            int b = e >> 3, j = e & 7;
            float gi = gsm[b*36 + j]      + xr[i][0];
            float gf = gsm[b*36 + 8 + j]  + xr[i][1];
            float gg = gsm[b*36 + 16 + j] + xr[i][2];
            float go = gsm[b*36 + 24 + j] + xr[i][3];
            float ig = sigf(gi);
            float fg = sigf(gf);
            float gv = tanh_f(gg);
            float og = sigf(go);
            float cn = fg*c_r[i] + ig*gv;
            c_r[i] = cn;
            float hn = og*tanh_f(cn);
            int gidx = bj[i];
            out[(size_t)t*(NB*HID) + gidx] = hn;
            hmn[gidx] = f2tf(hn * mh_r[i]);
            if (t == SEQ - 1) {
                out[SBH + gidx]           = hn;   // h_n
                out[SBH + NB*HID + gidx]  = cn;   // c_n
            }
        }

        // grid-wide barrier between steps (cooperative-groups pattern)
        if (t < SEQ - 1) {
            __syncthreads();
            if (tid == 0) {
                bar_red_release(&g_bar[t]);
                while (bar_ld_acquire(&g_bar[t]) < NCTA) { }
            }
            __syncthreads();
        }
    }
}

extern "C" void kernel_launch(void* const* d_in, const int* in_sizes, int n_in,
                              void* d_out, int out_size) {
    const float* x      = (const float*)d_in[0];
    const float* h0     = (const float*)d_in[1];
    const float* c0     = (const float*)d_in[2];
    const float* mask_x = (const float*)d_in[3];
    const float* mask_h = (const float*)d_in[4];
    const float* W_ih   = (const float*)d_in[5];
    const float* W_hh   = (const float*)d_in[6];
    const float* b_ih   = (const float*)d_in[7];
    const float* b_hh   = (const float*)d_in[8];
    float* out = (float*)d_out;

    const int smem = (32*WSTR + 2*ATILE + 64*36) * 4;  // 176,128 bytes
    cudaFuncSetAttribute(k_rnn, cudaFuncAttributeMaxDynamicSharedMemorySize, smem);

    k_maskx<<<(SEQ*NB*INP)/(256*4), 256>>>(x, mask_x);
    k_setup<<<(NB*HID)/256, 256>>>(h0, mask_h);
    k_wprep<<<(NCTA*32*HID)/1024, 256>>>(W_hh);
    k_gemm_x<<<dim3(NG/128, (SEQ*NB)/128), 256>>>(W_ih, b_ih, b_hh);
    k_rnn<<<NCTA, 256, smem>>>(c0, mask_h, out);
    (void)in_sizes; (void)n_in; (void)out_size;
}

// round 4
// speedup vs baseline: 2.7432x; 2.2527x over previous
#include <cuda_runtime.h>
#include <cstdint>

#define SEQ   256
#define NB    64
#define INP   1024
#define HID   1024
#define NG    4096   // 4*HID
#define SBH   (SEQ*NB*HID)
#define NCTA  128
#define GST   33          // gsm row stride (floats)
#define GSZ   (64*GST)    // per-kq gate region

// ---- device scratch ----
__device__ float    g_xm[(size_t)SEQ*NB*INP];   // x * mask_x
__device__ float    g_xg[(size_t)SEQ*NB*NG];    // input gate projections
__device__ uint32_t g_hm[2][NB*HID];            // masked h, tf32 bits, FRAGMENT-QUAD layout
__device__ uint32_t g_wt[(size_t)NCTA*32768];   // per-CTA W_hh tiles, tf32, pair-packed
__device__ int      g_bar[SEQ];                 // grid barrier counters

__device__ __forceinline__ uint32_t f2tf(float f) {
    uint32_t u;
    asm("cvt.rna.tf32.f32 %0, %1;" : "=r"(u) : "f"(f));
    return u;
}
__device__ __forceinline__ void mma8(float* d, const uint32_t* a, const uint32_t* b) {
    asm volatile(
        "mma.sync.aligned.m16n8k8.row.col.f32.tf32.tf32.f32 "
        "{%0,%1,%2,%3},{%4,%5,%6,%7},{%8,%9},{%0,%1,%2,%3};\n"
        : "+f"(d[0]), "+f"(d[1]), "+f"(d[2]), "+f"(d[3])
        : "r"(a[0]), "r"(a[1]), "r"(a[2]), "r"(a[3]), "r"(b[0]), "r"(b[1]));
}
__device__ __forceinline__ float sigf(float x)  { return 1.f/(1.f+__expf(-x)); }
__device__ __forceinline__ float tanh_f(float x){ return 2.f/(1.f+__expf(-2.f*x)) - 1.f; }
__device__ __forceinline__ void bar_red_release(int* p) {
    asm volatile("red.release.gpu.global.add.s32 [%0], 1;" :: "l"(p) : "memory");
}
__device__ __forceinline__ int bar_ld_acquire(int* p) {
    int v;
    asm volatile("ld.acquire.gpu.global.b32 %0, [%1];" : "=r"(v) : "l"(p) : "memory");
    return v;
}
// h quad-layout address (in words) for element (batch b, unit u)
__device__ __forceinline__ int hq_addr(int b, int u) {
    return (b>>4)*16384 + (u>>3)*128 + (b&7)*16 + (u&3)*4 + (((u>>2)&1)<<1) + ((b>>3)&1);
}

// ---- x * mask_x ----
__global__ void k_maskx(const float* __restrict__ x, const float* __restrict__ mx) {
    size_t i = ((size_t)blockIdx.x*256 + threadIdx.x)*4;
    float4 v = *reinterpret_cast<const float4*>(x + i);
    float4 m = *reinterpret_cast<const float4*>(mx + (i & 65535));
    v.x*=m.x; v.y*=m.y; v.z*=m.z; v.w*=m.w;
    *reinterpret_cast<float4*>(g_xm + i) = v;
}

// ---- init: hm0 = tf32(h0*mask_h) in quad layout; zero barrier counters ----
__global__ void k_setup(const float* __restrict__ h0, const float* __restrict__ mh) {
    int i = blockIdx.x*256 + threadIdx.x;
    int b = i >> 10, u = i & 1023;
    g_hm[0][hq_addr(b, u)] = f2tf(h0[i]*mh[i]);
    if (blockIdx.x == 0) g_bar[threadIdx.x] = 0;
}

// ---- W_hh prep: per-CTA tiles, tf32, pair-packed for LDS.64 B-frags ----
__global__ void k_wprep(const float* __restrict__ W) {
    int base = (blockIdx.x*256 + threadIdx.x)*4;
    #pragma unroll
    for (int e = 0; e < 4; e++) {
        int idx = base + e;
        int cb = idx >> 15;
        int dd = idx & 32767;
        int g  = dd >> 13;
        int ko = (dd >> 6) & 127;
        int j  = (dd >> 3) & 7;
        int q4 = (dd >> 1) & 3;
        int kh = dd & 1;
        g_wt[idx] = f2tf(W[((size_t)(g*HID + cb*8 + j))*HID + ko*8 + q4 + kh*4]);
    }
}

// ---- input projection GEMM (unchanged, passing) ----
__global__ void __launch_bounds__(256) k_gemm_x(const float* __restrict__ W,
                                                const float* __restrict__ b_ih,
                                                const float* __restrict__ b_hh) {
    __shared__ uint32_t sA[128*36];
    __shared__ uint32_t sB[128*36];
    const int tid  = threadIdx.x;
    const int lane = tid & 31;
    const int w    = tid >> 5;
    const int wm   = (w & 1) * 64;
    const int wn   = (w >> 1) * 32;
    const int m0   = blockIdx.y * 128;
    const int n0   = blockIdx.x * 128;

    const int rbase = tid >> 3;
    const int kq    = tid & 7;

    float acc[4][4][4];
    #pragma unroll
    for (int i = 0; i < 4; i++)
        #pragma unroll
        for (int j = 0; j < 4; j++)
            #pragma unroll
            for (int e = 0; e < 4; e++) acc[i][j][e] = 0.f;

    float4 a4[4], b4[4];
    {
        const int col = kq*4;
        #pragma unroll
        for (int r = 0; r < 4; r++) {
            const int row = rbase + 32*r;
            a4[r] = *reinterpret_cast<const float4*>(g_xm + (size_t)(m0+row)*INP + col);
            b4[r] = *reinterpret_cast<const float4*>(W    + (size_t)(n0+row)*INP + col);
        }
    }

    for (int kc = 0; kc < 32; ++kc) {
        __syncthreads();
        #pragma unroll
        for (int r = 0; r < 4; r++) {
            const int row = rbase + 32*r;
            const float* av = reinterpret_cast<const float*>(&a4[r]);
            const float* bv = reinterpret_cast<const float*>(&b4[r]);
            #pragma unroll
            for (int e = 0; e < 4; e++) {
                sA[row*36 + kq*4 + e] = f2tf(av[e]);
                sB[row*36 + kq*4 + e] = f2tf(bv[e]);
            }
        }
        __syncthreads();
        if (kc + 1 < 32) {
            const int col = (kc+1)*32 + kq*4;
            #pragma unroll
            for (int r = 0; r < 4; r++) {
                const int row = rbase + 32*r;
                a4[r] = *reinterpret_cast<const float4*>(g_xm + (size_t)(m0+row)*INP + col);
                b4[r] = *reinterpret_cast<const float4*>(W    + (size_t)(n0+row)*INP + col);
            }
        }
        #pragma unroll
        for (int kk = 0; kk < 4; ++kk) {
            uint32_t af[4][4];
            #pragma unroll
            for (int mt = 0; mt < 4; mt++) {
                const int r = wm + mt*16 + (lane>>2);
                const int c = kk*8 + (lane&3);
                af[mt][0] = sA[r*36 + c];
                af[mt][1] = sA[(r+8)*36 + c];
                af[mt][2] = sA[r*36 + c + 4];
                af[mt][3] = sA[(r+8)*36 + c + 4];
            }
            #pragma unroll
            for (int nt = 0; nt < 4; nt++) {
                const int rn = wn + nt*8 + (lane>>2);
                uint32_t bf[2];
                bf[0] = sB[rn*36 + kk*8 + (lane&3)];
                bf[1] = sB[rn*36 + kk*8 + (lane&3) + 4];
                #pragma unroll
                for (int mt = 0; mt < 4; mt++) mma8(acc[mt][nt], af[mt], bf);
            }
        }
    }

    #pragma unroll
    for (int mt = 0; mt < 4; mt++) {
        #pragma unroll
        for (int nt = 0; nt < 4; nt++) {
            const int gr = m0 + wm + mt*16 + (lane>>2);
            const int gc = n0 + wn + nt*8 + (lane&3)*2;
            const float bb0 = b_ih[gc]   + b_hh[gc];
            const float bb1 = b_ih[gc+1] + b_hh[gc+1];
            float* o = g_xg + (size_t)gr*NG + gc;
            o[0] = acc[mt][nt][0] + bb0;
            o[1] = acc[mt][nt][1] + bb1;
            o += (size_t)8*NG;
            o[0] = acc[mt][nt][2] + bb0;
            o[1] = acc[mt][nt][3] + bb1;
        }
    }
}

// ---- persistent recurrence kernel (R4) ----
__global__ void __launch_bounds__(256, 1) k_rnn(const float* __restrict__ c0,
                                                const float* __restrict__ mh,
                                                float* __restrict__ out) {
    extern __shared__ uint32_t sm[];
    uint32_t* sW  = sm;                    // 32768 words (128 KB)
    float*    gsm = (float*)(sm + 32768);  // 4 * GSZ words

    const int cb   = blockIdx.x;
    const int tid  = threadIdx.x;
    const int lane = tid & 31;
    const int w    = tid >> 5;
    const int half = w & 1;                // batch half
    const int kq   = w >> 1;               // k quarter
    const int lq   = lane >> 2;
    const int q4   = lane & 3;

    {
        const uint4* ws = reinterpret_cast<const uint4*>(g_wt + (size_t)cb*32768);
        uint4* wd = reinterpret_cast<uint4*>(sW);
        #pragma unroll
        for (int i = 0; i < 32; i++) wd[tid + i*256] = __ldcg(ws + tid + i*256);
    }

    float c_r[2], mh_r[2];
    int   bj[2];
    #pragma unroll
    for (int i = 0; i < 2; i++) {
        int e = tid + i*256;
        int b = e >> 3, j = e & 7;
        int gidx = b*HID + cb*8 + j;
        bj[i]   = gidx;
        c_r[i]  = c0[gidx];
        mh_r[i] = mh[gidx];
    }
    __syncthreads();

    for (int t = 0; t < SEQ; ++t) {
        const uint32_t* hmc = g_hm[t & 1];
        uint32_t*       hmn = g_hm[(t + 1) & 1];
        const float*    xgt = g_xg + (size_t)t*NB*NG;

        float xr[2][4];
        #pragma unroll
        for (int i = 0; i < 2; i++) {
            int e = tid + i*256;
            int b = e >> 3, j = e & 7;
            #pragma unroll
            for (int g = 0; g < 4; g++)
                xr[i][g] = __ldg(xgt + (size_t)b*NG + g*HID + cb*8 + j);
        }

        float acc[2][4][4];
        #pragma unroll
        for (int mt = 0; mt < 2; mt++)
            #pragma unroll
            for (int nt = 0; nt < 4; nt++)
                #pragma unroll
                for (int e = 0; e < 4; e++) acc[mt][nt][e] = 0.f;

        const uint4* aQ0 = reinterpret_cast<const uint4*>(hmc)
                         + ((half*2 + 0)*4096 + kq*1024 + lq*4 + q4);
        const uint4* aQ1 = aQ0 + 4096;

        uint4 afr[8][2];
        #pragma unroll
        for (int s = 0; s < 8; s++) {
            afr[s][0] = __ldcg(aQ0 + s*32);
            afr[s][1] = __ldcg(aQ1 + s*32);
        }

        #pragma unroll
        for (int g8 = 0; g8 < 4; g8++) {
            #pragma unroll
            for (int s = 0; s < 8; s++) {
                const int kk = g8*8 + s;
                uint4 A0 = afr[s][0], A1 = afr[s][1];
                if (g8 < 3) {
                    afr[s][0] = __ldcg(aQ0 + (kk+8)*32);
                    afr[s][1] = __ldcg(aQ1 + (kk+8)*32);
                }
                const int wb = (kq*32 + kk)*64 + lq*8 + q4*2;
                uint32_t af0[4] = {A0.x, A0.y, A0.z, A0.w};
                uint32_t af1[4] = {A1.x, A1.y, A1.z, A1.w};
                #pragma unroll
                for (int nt = 0; nt < 4; nt++) {
                    uint2 bb = *reinterpret_cast<const uint2*>(&sW[nt*8192 + wb]);
                    uint32_t bf[2] = {bb.x, bb.y};
                    mma8(acc[0][nt], af0, bf);
                    mma8(acc[1][nt], af1, bf);
                }
            }
        }

        {
            float* gp = gsm + kq*GSZ;
            #pragma unroll
            for (int mt = 0; mt < 2; mt++) {
                const int r0 = half*32 + mt*16 + lq;
                #pragma unroll
                for (int nt = 0; nt < 4; nt++) {
                    const int c = nt*8 + q4*2;
                    gp[r0*GST + c]       = acc[mt][nt][0];
                    gp[r0*GST + c + 1]   = acc[mt][nt][1];
                    gp[(r0+8)*GST + c]   = acc[mt][nt][2];
                    gp[(r0+8)*GST + c+1] = acc[mt][nt][3];
                }
            }
        }
        __syncthreads();

        #pragma unroll
        for (int i = 0; i < 2; i++) {
            int e = tid + i*256;
            int b = e >> 3, j = e & 7;
            float gt[4];
            #pragma unroll
            for (int g = 0; g < 4; g++) {
                int c = g*8 + j;
                gt[g] = gsm[0*GSZ + b*GST + c] + gsm[1*GSZ + b*GST + c]
                      + gsm[2*GSZ + b*GST + c] + gsm[3*GSZ + b*GST + c] + xr[i][g];
            }
            float ig = sigf(gt[0]);
            float fg = sigf(gt[1]);
            float gv = tanh_f(gt[2]);
            float og = sigf(gt[3]);
            float cn = fg*c_r[i] + ig*gv;
            c_r[i] = cn;
            float hn = og*tanh_f(cn);
            int gidx = bj[i];
            out[(size_t)t*(NB*HID) + gidx] = hn;
            hmn[hq_addr(b, cb*8 + j)] = f2tf(hn * mh_r[i]);
            if (t == SEQ - 1) {
                out[SBH + gidx]           = hn;
                out[SBH + NB*HID + gidx]  = cn;
            }
        }

        if (t < SEQ - 1) {
            __syncthreads();
            if (tid == 0) {
                bar_red_release(&g_bar[t]);
                while (bar_ld_acquire(&g_bar[t]) < NCTA) { }
            }
            __syncthreads();
        }
    }
}

extern "C" void kernel_launch(void* const* d_in, const int* in_sizes, int n_in,
                              void* d_out, int out_size) {
    const float* x      = (const float*)d_in[0];
    const float* h0     = (const float*)d_in[1];
    const float* c0     = (const float*)d_in[2];
    const float* mask_x = (const float*)d_in[3];
    const float* mask_h = (const float*)d_in[4];
    const float* W_ih   = (const float*)d_in[5];
    const float* W_hh   = (const float*)d_in[6];
    const float* b_ih   = (const float*)d_in[7];
    const float* b_hh   = (const float*)d_in[8];
    float* out = (float*)d_out;

    const int smem = (32768 + 4*GSZ) * 4;   // 164,864 bytes
    cudaFuncSetAttribute(k_rnn, cudaFuncAttributeMaxDynamicSharedMemorySize, smem);

    k_maskx<<<(SEQ*NB*INP)/(256*4), 256>>>(x, mask_x);
    k_setup<<<(NB*HID)/256, 256>>>(h0, mask_h);
    k_wprep<<<(NCTA*32768)/1024, 256>>>(W_hh);
    k_gemm_x<<<dim3(NG/128, (SEQ*NB)/128), 256>>>(W_ih, b_ih, b_hh);
    k_rnn<<<NCTA, 256, smem>>>(c0, mask_h, out);
    (void)in_sizes; (void)n_in; (void)out_size;
}

// round 5
// speedup vs baseline: 3.0503x; 1.1119x over previous
#include <cuda_runtime.h>
#include <cstdint>

#define SEQ   256
#define NB    64
#define INP   1024
#define HID   1024
#define NG    4096   // 4*HID
#define SBH   (SEQ*NB*HID)
#define NCTA  128
#define GST   33          // gsm row stride (floats)
#define GSZ   (64*GST)    // per-kq gate region

// gemm v2 tiling
#define ASTG  (128*40)    // words per A stage
#define BSTG  (256*40)    // words per B stage
#define SSTG  (ASTG+BSTG) // 15360 words per stage

// ---- device scratch ----
__device__ uint32_t g_xm[(size_t)SEQ*NB*INP];   // x*mask_x, tf32, pair-packed k
__device__ uint32_t g_wih[(size_t)NG*INP];      // W_ih, tf32, pair-packed, gate-interleaved rows
__device__ float    g_xg[(size_t)SEQ*NB*NG];    // input gate proj, gate-interleaved cols
__device__ uint32_t g_hm[2][NB*HID];            // masked h, tf32 bits, fragment-quad layout
__device__ uint32_t g_wt[(size_t)NCTA*32768];   // per-CTA W_hh tiles, tf32, pair-packed
__device__ int      g_bar[SEQ];                 // grid barrier counters

__device__ __forceinline__ uint32_t f2tf(float f) {
    uint32_t u;
    asm("cvt.rna.tf32.f32 %0, %1;" : "=r"(u) : "f"(f));
    return u;
}
__device__ __forceinline__ void mma8(float* d, const uint32_t* a, const uint32_t* b) {
    asm volatile(
        "mma.sync.aligned.m16n8k8.row.col.f32.tf32.tf32.f32 "
        "{%0,%1,%2,%3},{%4,%5,%6,%7},{%8,%9},{%0,%1,%2,%3};\n"
        : "+f"(d[0]), "+f"(d[1]), "+f"(d[2]), "+f"(d[3])
        : "r"(a[0]), "r"(a[1]), "r"(a[2]), "r"(a[3]), "r"(b[0]), "r"(b[1]));
}
__device__ __forceinline__ float sigf(float x)  { return 1.f/(1.f+__expf(-x)); }
__device__ __forceinline__ float tanh_f(float x){ return 2.f/(1.f+__expf(-2.f*x)) - 1.f; }
__device__ __forceinline__ void bar_red_release(int* p) {
    asm volatile("red.release.gpu.global.add.s32 [%0], 1;" :: "l"(p) : "memory");
}
__device__ __forceinline__ int bar_ld_acquire(int* p) {
    int v;
    asm volatile("ld.acquire.gpu.global.b32 %0, [%1];" : "=r"(v) : "l"(p) : "memory");
    return v;
}
__device__ __forceinline__ void cpa16(uint32_t d, const void* s) {
    asm volatile("cp.async.cg.shared.global [%0], [%1], 16;\n" :: "r"(d), "l"(s));
}
// h quad-layout address (words) for element (batch b, unit u)
__device__ __forceinline__ int hq_addr(int b, int u) {
    return (b>>4)*16384 + (u>>3)*128 + (b&7)*16 + (u&3)*4 + (((u>>2)&1)<<1) + ((b>>3)&1);
}

// ---- x*mask_x -> tf32, pair-packed k (pos q4*2+kh holds orig k = 8g+q4+4kh) ----
__global__ void k_maskx(const float* __restrict__ x, const float* __restrict__ mx) {
    int idx = blockIdx.x*256 + threadIdx.x;     // (m, k8-group)
    int m = idx >> 7, g8 = idx & 127;
    const float* xs = x  + (size_t)m*INP + g8*8;
    const float* ms = mx + (size_t)(m & 63)*INP + g8*8;
    float4 a = *reinterpret_cast<const float4*>(xs);
    float4 b = *reinterpret_cast<const float4*>(xs + 4);
    float4 u = *reinterpret_cast<const float4*>(ms);
    float4 v = *reinterpret_cast<const float4*>(ms + 4);
    uint4 o0, o1;
    o0.x = f2tf(a.x*u.x); o0.y = f2tf(b.x*v.x);
    o0.z = f2tf(a.y*u.y); o0.w = f2tf(b.y*v.y);
    o1.x = f2tf(a.z*u.z); o1.y = f2tf(b.z*v.z);
    o1.z = f2tf(a.w*u.w); o1.w = f2tf(b.w*v.w);
    uint4* d = reinterpret_cast<uint4*>(g_xm) + (size_t)idx*2;
    d[0] = o0; d[1] = o1;
}

// ---- W_ih -> tf32, pair-packed, row n' = u*4+g reads W[g*1024+u] ----
__global__ void k_wihprep(const float* __restrict__ W) {
    int idx = blockIdx.x*256 + threadIdx.x;     // (n', k8-group)
    int np = idx >> 7, g8 = idx & 127;
    int srow = (np & 3)*HID + (np >> 2);
    const float* s = W + (size_t)srow*INP + g8*8;
    float4 a = *reinterpret_cast<const float4*>(s);
    float4 b = *reinterpret_cast<const float4*>(s + 4);
    uint4 o0, o1;
    o0.x = f2tf(a.x); o0.y = f2tf(b.x); o0.z = f2tf(a.y); o0.w = f2tf(b.y);
    o1.x = f2tf(a.z); o1.y = f2tf(b.z); o1.z = f2tf(a.w); o1.w = f2tf(b.w);
    uint4* d = reinterpret_cast<uint4*>(g_wih) + (size_t)idx*2;
    d[0] = o0; d[1] = o1;
}

// ---- init: hm0 = tf32(h0*mask_h) quad layout; zero barriers ----
__global__ void k_setup(const float* __restrict__ h0, const float* __restrict__ mh) {
    int i = blockIdx.x*256 + threadIdx.x;
    int b = i >> 10, u = i & 1023;
    g_hm[0][hq_addr(b, u)] = f2tf(h0[i]*mh[i]);
    if (blockIdx.x == 0) g_bar[threadIdx.x] = 0;
}

// ---- W_hh prep: per-CTA tiles, tf32, pair-packed (unchanged, proven) ----
__global__ void k_wprep(const float* __restrict__ W) {
    int base = (blockIdx.x*256 + threadIdx.x)*4;
    #pragma unroll
    for (int e = 0; e < 4; e++) {
        int idx = base + e;
        int cb = idx >> 15;
        int dd = idx & 32767;
        int g  = dd >> 13;
        int ko = (dd >> 6) & 127;
        int j  = (dd >> 3) & 7;
        int q4 = (dd >> 1) & 3;
        int kh = dd & 1;
        g_wt[idx] = f2tf(W[((size_t)(g*HID + cb*8 + j))*HID + ko*8 + q4 + kh*4]);
    }
}

// ---- input projection GEMM v2: 128x256 CTA tile, 8 warps 64x64, 3-stage cp.async ----
__global__ void __launch_bounds__(256, 1) k_gemm_x(const float* __restrict__ b_ih,
                                                   const float* __restrict__ b_hh) {
    extern __shared__ uint32_t sg[];
    const int tid  = threadIdx.x;
    const int lane = tid & 31;
    const int w    = tid >> 5;
    const int wy   = w & 1;                 // m 64-half
    const int wx   = w >> 1;                // n 64-quarter
    const int lq   = lane >> 2;
    const int q4   = lane & 3;
    const int m0   = blockIdx.y * 128;
    const int n0   = blockIdx.x * 256;

    uint32_t sbase = (uint32_t)__cvta_generic_to_shared(sg);

    float acc[4][8][4];
    #pragma unroll
    for (int mt = 0; mt < 4; mt++)
        #pragma unroll
        for (int nt = 0; nt < 8; nt++)
            #pragma unroll
            for (int e = 0; e < 4; e++) acc[mt][nt][e] = 0.f;

    // stage issue: A 1024 segs (4/thread), B 2048 segs (8/thread), 16B each
    auto issue = [&](int st, int c) {
        const uint32_t stw = st*SSTG;
        #pragma unroll
        for (int j = 0; j < 4; j++) {
            int seg = tid + j*256;
            int row = seg >> 3, s8 = seg & 7;
            cpa16(sbase + (stw + row*40 + s8*4)*4,
                  g_xm + (size_t)(m0+row)*INP + c*32 + s8*4);
        }
        #pragma unroll
        for (int j = 0; j < 8; j++) {
            int seg = tid + j*256;
            int row = seg >> 3, s8 = seg & 7;
            cpa16(sbase + (stw + ASTG + row*40 + s8*4)*4,
                  g_wih + (size_t)(n0+row)*INP + c*32 + s8*4);
        }
    };

    #pragma unroll
    for (int s = 0; s < 3; s++) {
        issue(s, s);
        asm volatile("cp.async.commit_group;\n");
    }

    for (int c = 0; c < 32; ++c) {
        asm volatile("cp.async.wait_group 2;\n");
        __syncthreads();
        const uint32_t* sA = sg + (c % 3)*SSTG;
        const uint32_t* sB = sA + ASTG;
        #pragma unroll
        for (int kk = 0; kk < 4; kk++) {
            uint32_t af[4][4];
            #pragma unroll
            for (int mt = 0; mt < 4; mt++) {
                const int r = wy*64 + mt*16 + lq;
                uint2 ua = *reinterpret_cast<const uint2*>(&sA[r*40     + kk*8 + q4*2]);
                uint2 ub = *reinterpret_cast<const uint2*>(&sA[(r+8)*40 + kk*8 + q4*2]);
                af[mt][0] = ua.x; af[mt][1] = ub.x; af[mt][2] = ua.y; af[mt][3] = ub.y;
            }
            #pragma unroll
            for (int nt = 0; nt < 8; nt++) {
                const int rn = wx*64 + nt*8 + lq;
                uint2 bb = *reinterpret_cast<const uint2*>(&sB[rn*40 + kk*8 + q4*2]);
                uint32_t bf[2] = {bb.x, bb.y};
                #pragma unroll
                for (int mt = 0; mt < 4; mt++) mma8(acc[mt][nt], af[mt], bf);
            }
        }
        __syncthreads();
        if (c + 3 < 32) issue((c + 3) % 3, c + 3);
        asm volatile("cp.async.commit_group;\n");
    }

    // epilogue: + bias (remapped), write interleaved-gate xg
    #pragma unroll
    for (int mt = 0; mt < 4; mt++) {
        #pragma unroll
        for (int nt = 0; nt < 8; nt++) {
            const int gr = m0 + wy*64 + mt*16 + lq;
            const int gc = n0 + wx*64 + nt*8 + q4*2;
            const int s0 = (gc & 3)*HID + (gc >> 2);
            const int s1 = ((gc+1) & 3)*HID + ((gc+1) >> 2);
            const float bb0 = b_ih[s0] + b_hh[s0];
            const float bb1 = b_ih[s1] + b_hh[s1];
            float* o = g_xg + (size_t)gr*NG + gc;
            o[0] = acc[mt][nt][0] + bb0;
            o[1] = acc[mt][nt][1] + bb1;
            o += (size_t)8*NG;
            o[0] = acc[mt][nt][2] + bb0;
            o[1] = acc[mt][nt][3] + bb1;
        }
    }
}

// ---- persistent recurrence kernel (R4 core + float4 xg + split barrier) ----
__global__ void __launch_bounds__(256, 1) k_rnn(const float* __restrict__ c0,
                                                const float* __restrict__ mh,
                                                float* __restrict__ out) {
    extern __shared__ uint32_t sm[];
    uint32_t* sW  = sm;                    // 32768 words (128 KB)
    float*    gsm = (float*)(sm + 32768);  // 4 * GSZ words

    const int cb   = blockIdx.x;
    const int tid  = threadIdx.x;
    const int lane = tid & 31;
    const int w    = tid >> 5;
    const int half = w & 1;                // batch half
    const int kq   = w >> 1;               // k quarter
    const int lq   = lane >> 2;
    const int q4   = lane & 3;

    {
        const uint4* ws = reinterpret_cast<const uint4*>(g_wt + (size_t)cb*32768);
        uint4* wd = reinterpret_cast<uint4*>(sW);
        #pragma unroll
        for (int i = 0; i < 32; i++) wd[tid + i*256] = __ldcg(ws + tid + i*256);
    }

    float c_r[2], mh_r[2];
    int   bj[2];
    #pragma unroll
    for (int i = 0; i < 2; i++) {
        int e = tid + i*256;
        int b = e >> 3, j = e & 7;
        int gidx = b*HID + cb*8 + j;
        bj[i]   = gidx;
        c_r[i]  = c0[gidx];
        mh_r[i] = mh[gidx];
    }
    __syncthreads();

    // xg prefetch for t=0 (float4, interleaved-gate layout)
    float xr[2][4];
    {
        const float4* xg4 = reinterpret_cast<const float4*>(g_xg);
        #pragma unroll
        for (int i = 0; i < 2; i++) {
            int e = tid + i*256;
            int b = e >> 3, u = cb*8 + (e & 7);
            float4 q = __ldg(&xg4[(size_t)b*HID + u]);
            xr[i][0] = q.x; xr[i][1] = q.y; xr[i][2] = q.z; xr[i][3] = q.w;
        }
    }

    for (int t = 0; t < SEQ; ++t) {
        const uint32_t* hmc = g_hm[t & 1];
        uint32_t*       hmn = g_hm[(t + 1) & 1];

        float acc[2][4][4];
        #pragma unroll
        for (int mt = 0; mt < 2; mt++)
            #pragma unroll
            for (int nt = 0; nt < 4; nt++)
                #pragma unroll
                for (int e = 0; e < 4; e++) acc[mt][nt][e] = 0.f;

        const uint4* aQ0 = reinterpret_cast<const uint4*>(hmc)
                         + ((half*2 + 0)*4096 + kq*1024 + lq*4 + q4);
        const uint4* aQ1 = aQ0 + 4096;

        uint4 afr[8][2];
        #pragma unroll
        for (int s = 0; s < 8; s++) {
            afr[s][0] = __ldcg(aQ0 + s*32);
            afr[s][1] = __ldcg(aQ1 + s*32);
        }

        #pragma unroll
        for (int g8 = 0; g8 < 4; g8++) {
            #pragma unroll
            for (int s = 0; s < 8; s++) {
                const int kk = g8*8 + s;
                uint4 A0 = afr[s][0], A1 = afr[s][1];
                if (g8 < 3) {
                    afr[s][0] = __ldcg(aQ0 + (kk+8)*32);
                    afr[s][1] = __ldcg(aQ1 + (kk+8)*32);
                }
                const int wb = (kq*32 + kk)*64 + lq*8 + q4*2;
                uint32_t af0[4] = {A0.x, A0.y, A0.z, A0.w};
                uint32_t af1[4] = {A1.x, A1.y, A1.z, A1.w};
                #pragma unroll
                for (int nt = 0; nt < 4; nt++) {
                    uint2 bb = *reinterpret_cast<const uint2*>(&sW[nt*8192 + wb]);
                    uint32_t bf[2] = {bb.x, bb.y};
                    mma8(acc[0][nt], af0, bf);
                    mma8(acc[1][nt], af1, bf);
                }
            }
        }

        {
            float* gp = gsm + kq*GSZ;
            #pragma unroll
            for (int mt = 0; mt < 2; mt++) {
                const int r0 = half*32 + mt*16 + lq;
                #pragma unroll
                for (int nt = 0; nt < 4; nt++) {
                    const int c = nt*8 + q4*2;
                    gp[r0*GST + c]       = acc[mt][nt][0];
                    gp[r0*GST + c + 1]   = acc[mt][nt][1];
                    gp[(r0+8)*GST + c]   = acc[mt][nt][2];
                    gp[(r0+8)*GST + c+1] = acc[mt][nt][3];
                }
            }
        }
        __syncthreads();

        #pragma unroll
        for (int i = 0; i < 2; i++) {
            int e = tid + i*256;
            int b = e >> 3, j = e & 7;
            float gt[4];
            #pragma unroll
            for (int g = 0; g < 4; g++) {
                int c = g*8 + j;
                gt[g] = gsm[0*GSZ + b*GST + c] + gsm[1*GSZ + b*GST + c]
                      + gsm[2*GSZ + b*GST + c] + gsm[3*GSZ + b*GST + c] + xr[i][g];
            }
            float ig = sigf(gt[0]);
            float fg = sigf(gt[1]);
            float gv = tanh_f(gt[2]);
            float og = sigf(gt[3]);
            float cn = fg*c_r[i] + ig*gv;
            c_r[i] = cn;
            float hn = og*tanh_f(cn);
            int gidx = bj[i];
            out[(size_t)t*(NB*HID) + gidx] = hn;
            hmn[hq_addr(b, cb*8 + j)] = f2tf(hn * mh_r[i]);
            if (t == SEQ - 1) {
                out[SBH + gidx]           = hn;
                out[SBH + NB*HID + gidx]  = cn;
            }
        }

        if (t < SEQ - 1) {
            __syncthreads();                 // all hmn writes done CTA-wide
            if (tid == 0) bar_red_release(&g_bar[t]);   // arrive (release)

            // prefetch next step's xg while other CTAs arrive
            {
                const float4* xg4 = reinterpret_cast<const float4*>(g_xg)
                                  + (size_t)(t+1)*NB*HID;
                #pragma unroll
                for (int i = 0; i < 2; i++) {
                    int e = tid + i*256;
                    int b = e >> 3, u = cb*8 + (e & 7);
                    float4 q = __ldg(&xg4[(size_t)b*HID + u]);
                    xr[i][0] = q.x; xr[i][1] = q.y; xr[i][2] = q.z; xr[i][3] = q.w;
                }
            }

            if (tid == 0) {
                while (bar_ld_acquire(&g_bar[t]) < NCTA) { }
            }
            __syncthreads();
        }
    }
}

extern "C" void kernel_launch(void* const* d_in, const int* in_sizes, int n_in,
                              void* d_out, int out_size) {
    const float* x      = (const float*)d_in[0];
    const float* h0     = (const float*)d_in[1];
    const float* c0     = (const float*)d_in[2];
    const float* mask_x = (const float*)d_in[3];
    const float* mask_h = (const float*)d_in[4];
    const float* W_ih   = (const float*)d_in[5];
    const float* W_hh   = (const float*)d_in[6];
    const float* b_ih   = (const float*)d_in[7];
    const float* b_hh   = (const float*)d_in[8];
    float* out = (float*)d_out;

    const int smem_rnn  = (32768 + 4*GSZ) * 4;   // 164,864 B
    const int smem_gemm = 3 * SSTG * 4;          // 184,320 B
    cudaFuncSetAttribute(k_rnn,    cudaFuncAttributeMaxDynamicSharedMemorySize, smem_rnn);
    cudaFuncSetAttribute(k_gemm_x, cudaFuncAttributeMaxDynamicSharedMemorySize, smem_gemm);

    k_maskx<<<(SEQ*NB*INP)/(256*8), 256>>>(x, mask_x);           // 8192 blocks
    k_wihprep<<<(NG*INP)/(256*8), 256>>>(W_ih);                  // 2048 blocks
    k_setup<<<(NB*HID)/256, 256>>>(h0, mask_h);
    k_wprep<<<(NCTA*32768)/1024, 256>>>(W_hh);
    k_gemm_x<<<dim3(NG/256, (SEQ*NB)/128), 256, smem_gemm>>>(b_ih, b_hh);
    k_rnn<<<NCTA, 256, smem_rnn>>>(c0, mask_h, out);
    (void)in_sizes; (void)n_in; (void)out_size;
}

// round 7
// speedup vs baseline: 3.4226x; 1.1221x over previous
#include <cuda_runtime.h>
#include <cuda_fp16.h>
#include <cstdint>

#define SEQ   256
#define NB    64
#define INP   1024
#define HID   1024
#define NG    4096   // 4*HID
#define SBH   (SEQ*NB*HID)
#define NCTA  128
#define GST   33          // gsm row stride (floats)
#define GSZ   (64*GST)    // per-kq gate region

// gemm v2 tiling (unchanged)
#define ASTG  (128*40)
#define BSTG  (256*40)
#define SSTG  (ASTG+BSTG)

// ---- device scratch ----
__device__ uint32_t g_xm[(size_t)SEQ*NB*INP];   // x*mask_x, tf32, pair-packed k
__device__ uint32_t g_wih[(size_t)NG*INP];      // W_ih, tf32, pair-packed, gate-interleaved rows
__device__ float    g_xg[(size_t)SEQ*NB*NG];    // input gate proj, gate-interleaved cols
__device__ uint32_t g_hm[2][NB*HID/2];          // masked h, fp16x2, mma-fragment layout
__device__ uint32_t g_wt[(size_t)NCTA*16384];   // per-CTA W_hh tiles, fp16x2, B-frag layout
__device__ int      g_bar[SEQ];                 // grid barrier counters

__device__ __forceinline__ uint32_t f2tf(float f) {
    uint32_t u;
    asm("cvt.rna.tf32.f32 %0, %1;" : "=r"(u) : "f"(f));
    return u;
}
__device__ __forceinline__ void mma8(float* d, const uint32_t* a, const uint32_t* b) {
    asm volatile(
        "mma.sync.aligned.m16n8k8.row.col.f32.tf32.tf32.f32 "
        "{%0,%1,%2,%3},{%4,%5,%6,%7},{%8,%9},{%0,%1,%2,%3};\n"
        : "+f"(d[0]), "+f"(d[1]), "+f"(d[2]), "+f"(d[3])
        : "r"(a[0]), "r"(a[1]), "r"(a[2]), "r"(a[3]), "r"(b[0]), "r"(b[1]));
}
__device__ __forceinline__ void mma16h(float* d, const uint32_t* a, const uint32_t* b) {
    asm volatile(
        "mma.sync.aligned.m16n8k16.row.col.f32.f16.f16.f32 "
        "{%0,%1,%2,%3},{%4,%5,%6,%7},{%8,%9},{%0,%1,%2,%3};\n"
        : "+f"(d[0]), "+f"(d[1]), "+f"(d[2]), "+f"(d[3])
        : "r"(a[0]), "r"(a[1]), "r"(a[2]), "r"(a[3]), "r"(b[0]), "r"(b[1]));
}
__device__ __forceinline__ float sigf(float x)  { return 1.f/(1.f+__expf(-x)); }
__device__ __forceinline__ float tanh_f(float x){ return 2.f/(1.f+__expf(-2.f*x)) - 1.f; }
__device__ __forceinline__ void bar_red_release(int* p) {
    asm volatile("red.release.gpu.global.add.s32 [%0], 1;" :: "l"(p) : "memory");
}
__device__ __forceinline__ int bar_ld_acquire(int* p) {
    int v;
    asm volatile("ld.acquire.gpu.global.b32 %0, [%1];" : "=r"(v) : "l"(p) : "memory");
    return v;
}
__device__ __forceinline__ void cpa16(uint32_t d, const void* s) {
    asm volatile("cp.async.cg.shared.global [%0], [%1], 16;\n" :: "r"(d), "l"(s));
}
__device__ __forceinline__ uint32_t packh2(float lo, float hi) {
    __half2 h = __floats2half2_rn(lo, hi);   // lo -> low 16 bits (even k)
    return *reinterpret_cast<uint32_t*>(&h);
}
// fp16 h layout: word address for (batch b, k-pair pk); pk = k/2
__device__ __forceinline__ int hp_addr(int b, int pk) {
    int mt = b >> 4, rb = b & 15;
    int c  = pk >> 3, pkl = pk & 7;
    int lane = (rb & 7)*4 + (pkl & 3);
    int e    = (pkl >> 2)*2 + (rb >> 3);
    return (mt*64 + c)*128 + lane*4 + e;
}

// ---- x*mask_x -> tf32, pair-packed k (unchanged, proven) ----
__global__ void k_maskx(const float* __restrict__ x, const float* __restrict__ mx) {
    int idx = blockIdx.x*256 + threadIdx.x;
    int m = idx >> 7, g8 = idx & 127;
    const float* xs = x  + (size_t)m*INP + g8*8;
    const float* ms = mx + (size_t)(m & 63)*INP + g8*8;
    float4 a = *reinterpret_cast<const float4*>(xs);
    float4 b = *reinterpret_cast<const float4*>(xs + 4);
    float4 u = *reinterpret_cast<const float4*>(ms);
    float4 v = *reinterpret_cast<const float4*>(ms + 4);
    uint4 o0, o1;
    o0.x = f2tf(a.x*u.x); o0.y = f2tf(b.x*v.x);
    o0.z = f2tf(a.y*u.y); o0.w = f2tf(b.y*v.y);
    o1.x = f2tf(a.z*u.z); o1.y = f2tf(b.z*v.z);
    o1.z = f2tf(a.w*u.w); o1.w = f2tf(b.w*v.w);
    uint4* d = reinterpret_cast<uint4*>(g_xm) + (size_t)idx*2;
    d[0] = o0; d[1] = o1;
}

// ---- W_ih -> tf32 pair-packed gate-interleaved (unchanged, proven) ----
__global__ void k_wihprep(const float* __restrict__ W) {
    int idx = blockIdx.x*256 + threadIdx.x;
    int np = idx >> 7, g8 = idx & 127;
    int srow = (np & 3)*HID + (np >> 2);
    const float* s = W + (size_t)srow*INP + g8*8;
    float4 a = *reinterpret_cast<const float4*>(s);
    float4 b = *reinterpret_cast<const float4*>(s + 4);
    uint4 o0, o1;
    o0.x = f2tf(a.x); o0.y = f2tf(b.x); o0.z = f2tf(a.y); o0.w = f2tf(b.y);
    o1.x = f2tf(a.z); o1.y = f2tf(b.z); o1.z = f2tf(a.w); o1.w = f2tf(b.w);
    uint4* d = reinterpret_cast<uint4*>(g_wih) + (size_t)idx*2;
    d[0] = o0; d[1] = o1;
}

// ---- init: hm0 = fp16x2(h0*mask_h) in frag layout; zero barriers ----
__global__ void k_setup(const float* __restrict__ h0, const float* __restrict__ mh) {
    int i = blockIdx.x*256 + threadIdx.x;     // 32768 words
    int b = i >> 9, pk = i & 511;
    int u0 = pk*2;
    int s = b*HID + u0;
    float v0 = h0[s]   * mh[s];
    float v1 = h0[s+1] * mh[s+1];
    g_hm[0][hp_addr(b, pk)] = packh2(v0, v1);
    if (blockIdx.x == 0) g_bar[threadIdx.x] = 0;
}

// ---- W_hh prep: per-CTA fp16x2 tiles in B-fragment layout ----
// dst word (within CTA): blk*128 + lane*4 + e, blk = chunk*2 + ntp  [128-word blocks]
//   nt = ntp*2 + (e>>1), pk_off = q4 + (e&1)*4
//   col n = nt*8+lq -> gate g=n>>3, unit j=n&7 -> W row g*HID + cb*8 + j
__global__ void k_wprep(const float* __restrict__ W) {
    int gi = blockIdx.x*256 + threadIdx.x;    // NCTA*16384 words
    int cb = gi >> 14;
    int d  = gi & 16383;
    int blk = d >> 7;                         // FIX (R6 bug): 128-word blocks
    int lane_e = d & 127;                     // FIX (R6 bug)
    int chunk = blk >> 1, ntp = blk & 1;
    int lane = lane_e >> 2, e = lane_e & 3;
    int lq = lane >> 2, q4 = lane & 3;
    int nt = ntp*2 + (e >> 1);
    int pk_off = q4 + (e & 1)*4;
    int n = nt*8 + lq;
    int g = n >> 3, j = n & 7;
    const float* src = W + ((size_t)(g*HID + cb*8 + j))*HID + (chunk*8 + pk_off)*2;
    g_wt[gi] = packh2(src[0], src[1]);
}

// ---- input projection GEMM v2 (unchanged, proven) ----
__global__ void __launch_bounds__(256, 1) k_gemm_x(const float* __restrict__ b_ih,
                                                   const float* __restrict__ b_hh) {
    extern __shared__ uint32_t sg[];
    const int tid  = threadIdx.x;
    const int lane = tid & 31;
    const int w    = tid >> 5;
    const int wy   = w & 1;
    const int wx   = w >> 1;
    const int lq   = lane >> 2;
    const int q4   = lane & 3;
    const int m0   = blockIdx.y * 128;
    const int n0   = blockIdx.x * 256;

    uint32_t sbase = (uint32_t)__cvta_generic_to_shared(sg);

    float acc[4][8][4];
    #pragma unroll
    for (int mt = 0; mt < 4; mt++)
        #pragma unroll
        for (int nt = 0; nt < 8; nt++)
            #pragma unroll
            for (int e = 0; e < 4; e++) acc[mt][nt][e] = 0.f;

    auto issue = [&](int st, int c) {
        const uint32_t stw = st*SSTG;
        #pragma unroll
        for (int j = 0; j < 4; j++) {
            int seg = tid + j*256;
            int row = seg >> 3, s8 = seg & 7;
            cpa16(sbase + (stw + row*40 + s8*4)*4,
                  g_xm + (size_t)(m0+row)*INP + c*32 + s8*4);
        }
        #pragma unroll
        for (int j = 0; j < 8; j++) {
            int seg = tid + j*256;
            int row = seg >> 3, s8 = seg & 7;
            cpa16(sbase + (stw + ASTG + row*40 + s8*4)*4,
                  g_wih + (size_t)(n0+row)*INP + c*32 + s8*4);
        }
    };

    #pragma unroll
    for (int s = 0; s < 3; s++) {
        issue(s, s);
        asm volatile("cp.async.commit_group;\n");
    }

    for (int c = 0; c < 32; ++c) {
        asm volatile("cp.async.wait_group 2;\n");
        __syncthreads();
        const uint32_t* sA = sg + (c % 3)*SSTG;
        const uint32_t* sB = sA + ASTG;
        #pragma unroll
        for (int kk = 0; kk < 4; kk++) {
            uint32_t af[4][4];
            #pragma unroll
            for (int mt = 0; mt < 4; mt++) {
                const int r = wy*64 + mt*16 + lq;
                uint2 ua = *reinterpret_cast<const uint2*>(&sA[r*40     + kk*8 + q4*2]);
                uint2 ub = *reinterpret_cast<const uint2*>(&sA[(r+8)*40 + kk*8 + q4*2]);
                af[mt][0] = ua.x; af[mt][1] = ub.x; af[mt][2] = ua.y; af[mt][3] = ub.y;
            }
            #pragma unroll
            for (int nt = 0; nt < 8; nt++) {
                const int rn = wx*64 + nt*8 + lq;
                uint2 bb = *reinterpret_cast<const uint2*>(&sB[rn*40 + kk*8 + q4*2]);
                uint32_t bf[2] = {bb.x, bb.y};
                #pragma unroll
                for (int mt = 0; mt < 4; mt++) mma8(acc[mt][nt], af[mt], bf);
            }
        }
        __syncthreads();
        if (c + 3 < 32) issue((c + 3) % 3, c + 3);
        asm volatile("cp.async.commit_group;\n");
    }

    #pragma unroll
    for (int mt = 0; mt < 4; mt++) {
        #pragma unroll
        for (int nt = 0; nt < 8; nt++) {
            const int gr = m0 + wy*64 + mt*16 + lq;
            const int gc = n0 + wx*64 + nt*8 + q4*2;
            const int s0 = (gc & 3)*HID + (gc >> 2);
            const int s1 = ((gc+1) & 3)*HID + ((gc+1) >> 2);
            const float bb0 = b_ih[s0] + b_hh[s0];
            const float bb1 = b_ih[s1] + b_hh[s1];
            float* o = g_xg + (size_t)gr*NG + gc;
            o[0] = acc[mt][nt][0] + bb0;
            o[1] = acc[mt][nt][1] + bb1;
            o += (size_t)8*NG;
            o[0] = acc[mt][nt][2] + bb0;
            o[1] = acc[mt][nt][3] + bb1;
        }
    }
}

// ---- persistent recurrence kernel (fp16 operands, fp32 accumulate) ----
__global__ void __launch_bounds__(256, 1) k_rnn(const float* __restrict__ c0,
                                                const float* __restrict__ mh,
                                                float* __restrict__ out) {
    extern __shared__ uint32_t sm[];
    uint32_t* sW  = sm;                    // 16384 words (64 KB)
    float*    gsm = (float*)(sm + 16384);  // 4 * GSZ words

    const int cb   = blockIdx.x;
    const int tid  = threadIdx.x;
    const int lane = tid & 31;
    const int w    = tid >> 5;
    const int half = w & 1;                // batch half
    const int kq   = w >> 1;               // k quarter (256 k = 16 chunks)

    // preload fp16 W tile (16384 words = 4096 uint4)
    {
        const uint4* ws = reinterpret_cast<const uint4*>(g_wt + (size_t)cb*16384);
        uint4* wd = reinterpret_cast<uint4*>(sW);
        #pragma unroll
        for (int i = 0; i < 16; i++) wd[tid + i*256] = __ldcg(ws + tid + i*256);
    }

    // cell mapping: thread -> (batch pb, unit-pair p); units u0=cb*8+2p, u0+1
    const int pb = tid >> 2;
    const int p  = tid & 3;
    const int u0 = cb*8 + 2*p;
    const int gbase = pb*HID + u0;

    float2 c_r  = *reinterpret_cast<const float2*>(c0 + gbase);
    float2 mh2  = *reinterpret_cast<const float2*>(mh + gbase);
    const int hwaddr = hp_addr(pb, cb*4 + p);
    __syncthreads();

    // xg prefetch for t=0
    float xr[2][4];
    {
        const float4* xg4 = reinterpret_cast<const float4*>(g_xg);
        #pragma unroll
        for (int i = 0; i < 2; i++) {
            float4 q = __ldg(&xg4[(size_t)pb*HID + u0 + i]);
            xr[i][0] = q.x; xr[i][1] = q.y; xr[i][2] = q.z; xr[i][3] = q.w;
        }
    }

    const uint4* wsm4 = reinterpret_cast<const uint4*>(sW);

    for (int t = 0; t < SEQ; ++t) {
        const uint4* h4 = reinterpret_cast<const uint4*>(g_hm[t & 1]);
        uint32_t*    hmn = g_hm[(t + 1) & 1];

        float acc[2][4][4];
        #pragma unroll
        for (int mt = 0; mt < 2; mt++)
            #pragma unroll
            for (int nt = 0; nt < 4; nt++)
                #pragma unroll
                for (int e = 0; e < 4; e++) acc[mt][nt][e] = 0.f;

        // A-frag pointers: tile tmt = half*2+mt, chunk stride 32 uint4
        const uint4* ap0 = h4 + (half*2 + 0)*2048 + kq*512 + lane;
        const uint4* ap1 = ap0 + 2048;

        uint4 afr[8][2];
        #pragma unroll
        for (int s = 0; s < 8; s++) {
            afr[s][0] = __ldcg(ap0 + s*32);
            afr[s][1] = __ldcg(ap1 + s*32);
        }

        #pragma unroll
        for (int g8 = 0; g8 < 2; g8++) {
            #pragma unroll
            for (int s = 0; s < 8; s++) {
                const int cq = g8*8 + s;
                uint4 A0 = afr[s][0], A1 = afr[s][1];
                if (g8 == 0) {
                    afr[s][0] = __ldcg(ap0 + (cq+8)*32);
                    afr[s][1] = __ldcg(ap1 + (cq+8)*32);
                }
                const int bidx = (kq*16 + cq)*64 + lane;   // uint4 units
                uint4 b01 = wsm4[bidx];
                uint4 b23 = wsm4[bidx + 32];
                uint32_t af0[4] = {A0.x, A0.y, A0.z, A0.w};
                uint32_t af1[4] = {A1.x, A1.y, A1.z, A1.w};
                uint32_t bf0[2] = {b01.x, b01.y};
                uint32_t bf1[2] = {b01.z, b01.w};
                uint32_t bf2[2] = {b23.x, b23.y};
                uint32_t bf3[2] = {b23.z, b23.w};
                mma16h(acc[0][0], af0, bf0); mma16h(acc[1][0], af1, bf0);
                mma16h(acc[0][1], af0, bf1); mma16h(acc[1][1], af1, bf1);
                mma16h(acc[0][2], af0, bf2); mma16h(acc[1][2], af1, bf2);
                mma16h(acc[0][3], af0, bf3); mma16h(acc[1][3], af1, bf3);
            }
        }

        // stage split-K partial gates
        {
            const int lq = lane >> 2, q4 = lane & 3;
            float* gp = gsm + kq*GSZ;
            #pragma unroll
            for (int mt = 0; mt < 2; mt++) {
                const int r0 = half*32 + mt*16 + lq;
                #pragma unroll
                for (int nt = 0; nt < 4; nt++) {
                    const int c = nt*8 + q4*2;
                    gp[r0*GST + c]       = acc[mt][nt][0];
                    gp[r0*GST + c + 1]   = acc[mt][nt][1];
                    gp[(r0+8)*GST + c]   = acc[mt][nt][2];
                    gp[(r0+8)*GST + c+1] = acc[mt][nt][3];
                }
            }
        }
        __syncthreads();

        // fused LSTM cell: thread handles units (u0, u0+1) of batch pb
        float hnv[2], cnv[2];
        #pragma unroll
        for (int i = 0; i < 2; i++) {
            const int j = 2*p + i;            // local unit (0-7)
            float gt[4];
            #pragma unroll
            for (int g = 0; g < 4; g++) {
                const int c = g*8 + j;
                gt[g] = gsm[0*GSZ + pb*GST + c] + gsm[1*GSZ + pb*GST + c]
                      + gsm[2*GSZ + pb*GST + c] + gsm[3*GSZ + pb*GST + c] + xr[i][g];
            }
            float ig = sigf(gt[0]);
            float fg = sigf(gt[1]);
            float gv = tanh_f(gt[2]);
            float og = sigf(gt[3]);
            float cp = (i == 0) ? c_r.x : c_r.y;
            float cn = fg*cp + ig*gv;
            cnv[i] = cn;
            hnv[i] = og*tanh_f(cn);
        }
        c_r.x = cnv[0]; c_r.y = cnv[1];

        *reinterpret_cast<float2*>(out + (size_t)t*(NB*HID) + gbase)
            = make_float2(hnv[0], hnv[1]);
        hmn[hwaddr] = packh2(hnv[0]*mh2.x, hnv[1]*mh2.y);
        if (t == SEQ - 1) {
            *reinterpret_cast<float2*>(out + SBH + gbase)          = make_float2(hnv[0], hnv[1]);
            *reinterpret_cast<float2*>(out + SBH + NB*HID + gbase) = make_float2(cnv[0], cnv[1]);
        }

        if (t < SEQ - 1) {
            __syncthreads();                            // all hmn writes done CTA-wide
            if (tid == 0) bar_red_release(&g_bar[t]);   // arrive (release)

            // prefetch next step's xg while other CTAs arrive
            {
                const float4* xg4 = reinterpret_cast<const float4*>(g_xg)
                                  + (size_t)(t+1)*NB*HID;
                #pragma unroll
                for (int i = 0; i < 2; i++) {
                    float4 q = __ldg(&xg4[(size_t)pb*HID + u0 + i]);
                    xr[i][0] = q.x; xr[i][1] = q.y; xr[i][2] = q.z; xr[i][3] = q.w;
                }
            }

            if (tid == 0) {
                while (bar_ld_acquire(&g_bar[t]) < NCTA) { }
            }
            __syncthreads();
        }
    }
}

extern "C" void kernel_launch(void* const* d_in, const int* in_sizes, int n_in,
                              void* d_out, int out_size) {
    const float* x      = (const float*)d_in[0];
    const float* h0     = (const float*)d_in[1];
    const float* c0     = (const float*)d_in[2];
    const float* mask_x = (const float*)d_in[3];
    const float* mask_h = (const float*)d_in[4];
    const float* W_ih   = (const float*)d_in[5];
    const float* W_hh   = (const float*)d_in[6];
    const float* b_ih   = (const float*)d_in[7];
    const float* b_hh   = (const float*)d_in[8];
    float* out = (float*)d_out;

    const int smem_rnn  = (16384 + 4*GSZ) * 4;   // 99,328 B
    const int smem_gemm = 3 * SSTG * 4;          // 184,320 B
    cudaFuncSetAttribute(k_rnn,    cudaFuncAttributeMaxDynamicSharedMemorySize, smem_rnn);
    cudaFuncSetAttribute(k_gemm_x, cudaFuncAttributeMaxDynamicSharedMemorySize, smem_gemm);

    k_maskx<<<(SEQ*NB*INP)/(256*8), 256>>>(x, mask_x);
    k_wihprep<<<(NG*INP)/(256*8), 256>>>(W_ih);
    k_setup<<<(NB*HID/2)/256, 256>>>(h0, mask_h);
    k_wprep<<<(NCTA*16384)/256, 256>>>(W_hh);
    k_gemm_x<<<dim3(NG/256, (SEQ*NB)/128), 256, smem_gemm>>>(b_ih, b_hh);
    k_rnn<<<NCTA, 256, smem_rnn>>>(c0, mask_h, out);
    (void)in_sizes; (void)n_in; (void)out_size;
}

// round 8
// speedup vs baseline: 5.0470x; 1.4746x over previous
#include <cuda_runtime.h>
#include <cuda_fp16.h>
#include <cstdint>

#define SEQ   256
#define NB    64
#define INP   1024
#define HID   1024
#define SBH   (SEQ*NB*HID)
#define NCTA  128
#define GST   33          // gsm row stride (floats)
#define GSZ   (64*GST)    // per-kq gate region
#define WTILE 16384       // words per W tile per CTA (32 rows x 1024 k, fp16x2)

// ---- device scratch ----
__device__ uint32_t g_xv[(size_t)SEQ*NB*HID/2];  // x*mask_x, fp16x2, A-frag layout per step
__device__ uint32_t g_hm[2][NB*HID/2];           // masked h, fp16x2, A-frag layout
__device__ uint32_t g_wt[(size_t)2*NCTA*WTILE];  // [0]=W_hh tiles, [1]=W_ih tiles (B-frag)
__device__ int      g_bar[SEQ];                  // grid barrier counters

__device__ __forceinline__ void mma16h(float* d, const uint32_t* a, const uint32_t* b) {
    asm volatile(
        "mma.sync.aligned.m16n8k16.row.col.f32.f16.f16.f32 "
        "{%0,%1,%2,%3},{%4,%5,%6,%7},{%8,%9},{%0,%1,%2,%3};\n"
        : "+f"(d[0]), "+f"(d[1]), "+f"(d[2]), "+f"(d[3])
        : "r"(a[0]), "r"(a[1]), "r"(a[2]), "r"(a[3]), "r"(b[0]), "r"(b[1]));
}
__device__ __forceinline__ float sigf(float x)  { return 1.f/(1.f+__expf(-x)); }
__device__ __forceinline__ float tanh_f(float x){ return 2.f/(1.f+__expf(-2.f*x)) - 1.f; }
__device__ __forceinline__ void bar_red_release(int* p) {
    asm volatile("red.release.gpu.global.add.s32 [%0], 1;" :: "l"(p) : "memory");
}
__device__ __forceinline__ int bar_ld_acquire(int* p) {
    int v;
    asm volatile("ld.acquire.gpu.global.b32 %0, [%1];" : "=r"(v) : "l"(p) : "memory");
    return v;
}
__device__ __forceinline__ uint32_t packh2(float lo, float hi) {
    __half2 h = __floats2half2_rn(lo, hi);   // lo -> low 16 bits (even k)
    return *reinterpret_cast<uint32_t*>(&h);
}
// fp16 A-frag layout: word address for (batch b, k-pair pk); pk = k/2  (proven R7)
__device__ __forceinline__ int hp_addr(int b, int pk) {
    int mt = b >> 4, rb = b & 15;
    int c  = pk >> 3, pkl = pk & 7;
    int lane = (rb & 7)*4 + (pkl & 3);
    int e    = (pkl >> 2)*2 + (rb >> 3);
    return (mt*64 + c)*128 + lane*4 + e;
}

// ---- x*mask_x -> fp16x2 A-frag layout, per step (k_setup clone + t index) ----
__global__ void k_xprep(const float* __restrict__ x, const float* __restrict__ mx) {
    int i = blockIdx.x*256 + threadIdx.x;     // SEQ*32768 words total
    int t = i >> 15;
    int d = i & 32767;
    int b = d >> 9, pk = d & 511;
    int u0 = pk*2;
    const float* xs = x  + ((size_t)t*NB + b)*INP + u0;
    const float* ms = mx + (size_t)b*INP + u0;
    g_xv[(size_t)t*32768 + hp_addr(b, pk)] = packh2(xs[0]*ms[0], xs[1]*ms[1]);
}

// ---- init: hm0 = fp16x2(h0*mask_h) in frag layout; zero barriers (proven R7) ----
__global__ void k_setup(const float* __restrict__ h0, const float* __restrict__ mh) {
    int i = blockIdx.x*256 + threadIdx.x;
    int b = i >> 9, pk = i & 511;
    int u0 = pk*2;
    int s = b*HID + u0;
    g_hm[0][hp_addr(b, pk)] = packh2(h0[s]*mh[s], h0[s+1]*mh[s+1]);
    if (blockIdx.x == 0) g_bar[threadIdx.x] = 0;
}

// ---- W prep: per-CTA fp16x2 tiles in B-fragment layout (proven R7; runs for
// both W_hh (which=0) and W_ih (which=1) — identical [4H, K=1024] shape) ----
__global__ void k_wprep(const float* __restrict__ W, int which) {
    int gi = blockIdx.x*256 + threadIdx.x;    // NCTA*WTILE words
    int cb = gi >> 14;
    int d  = gi & 16383;
    int blk = d >> 7;                         // 128-word blocks
    int lane_e = d & 127;
    int chunk = blk >> 1, ntp = blk & 1;
    int lane = lane_e >> 2, e = lane_e & 3;
    int lq = lane >> 2, q4 = lane & 3;
    int nt = ntp*2 + (e >> 1);
    int pk_off = q4 + (e & 1)*4;
    int n = nt*8 + lq;
    int g = n >> 3, j = n & 7;
    const float* src = W + ((size_t)(g*HID + cb*8 + j))*HID + (chunk*8 + pk_off)*2;
    g_wt[(size_t)which*NCTA*WTILE + gi] = packh2(src[0], src[1]);
}

// one 1024-K mma pass: A-frags from ABASE (uint4, A-frag layout), B from W4 (SMEM)
#define MMA_BLOCK(ABASE, W4) do {                                              \
    const uint4* ap0 = (ABASE) + half*2*2048 + kq*512 + lane;                  \
    const uint4* ap1 = ap0 + 2048;                                             \
    uint4 afr[8][2];                                                           \
    _Pragma("unroll")                                                          \
    for (int s = 0; s < 8; s++) {                                              \
        afr[s][0] = __ldcg(ap0 + s*32);                                        \
        afr[s][1] = __ldcg(ap1 + s*32);                                        \
    }                                                                          \
    _Pragma("unroll")                                                          \
    for (int g8 = 0; g8 < 2; g8++) {                                           \
        _Pragma("unroll")                                                      \
        for (int s = 0; s < 8; s++) {                                          \
            const int cq = g8*8 + s;                                           \
            uint4 A0 = afr[s][0], A1 = afr[s][1];                              \
            if (g8 == 0) {                                                     \
                afr[s][0] = __ldcg(ap0 + (cq+8)*32);                           \
                afr[s][1] = __ldcg(ap1 + (cq+8)*32);                           \
            }                                                                  \
            const int bidx = (kq*16 + cq)*64 + lane;                           \
            uint4 b01 = (W4)[bidx];                                            \
            uint4 b23 = (W4)[bidx + 32];                                       \
            uint32_t af0[4] = {A0.x, A0.y, A0.z, A0.w};                        \
            uint32_t af1[4] = {A1.x, A1.y, A1.z, A1.w};                        \
            uint32_t bf0[2] = {b01.x, b01.y};                                  \
            uint32_t bf1[2] = {b01.z, b01.w};                                  \
            uint32_t bf2[2] = {b23.x, b23.y};                                  \
            uint32_t bf3[2] = {b23.z, b23.w};                                  \
            mma16h(acc[0][0], af0, bf0); mma16h(acc[1][0], af1, bf0);          \
            mma16h(acc[0][1], af0, bf1); mma16h(acc[1][1], af1, bf1);          \
            mma16h(acc[0][2], af0, bf2); mma16h(acc[1][2], af1, bf2);          \
            mma16h(acc[0][3], af0, bf3); mma16h(acc[1][3], af1, bf3);          \
        }                                                                      \
    }                                                                          \
} while (0)

// ---- fully fused persistent LSTM: gates = W_ih*x_t + W_hh*h_t + b, all in-kernel ----
__global__ void __launch_bounds__(256, 1) k_rnn(const float* __restrict__ c0,
                                                const float* __restrict__ mh,
                                                const float* __restrict__ b_ih,
                                                const float* __restrict__ b_hh,
                                                float* __restrict__ out) {
    extern __shared__ uint32_t sm[];
    uint32_t* sWh = sm;                    // W_hh tile, 16384 words
    uint32_t* sWi = sm + WTILE;            // W_ih tile, 16384 words
    float*    gsm = (float*)(sm + 2*WTILE);

    const int cb   = blockIdx.x;
    const int tid  = threadIdx.x;
    const int lane = tid & 31;
    const int w    = tid >> 5;
    const int half = w & 1;                // batch half
    const int kq   = w >> 1;               // k quarter

    // preload both W tiles (proven copy pattern)
    {
        const uint4* s0 = reinterpret_cast<const uint4*>(g_wt + (size_t)cb*WTILE);
        const uint4* s1 = reinterpret_cast<const uint4*>(g_wt + (size_t)(NCTA + cb)*WTILE);
        uint4* d0 = reinterpret_cast<uint4*>(sWh);
        uint4* d1 = reinterpret_cast<uint4*>(sWi);
        #pragma unroll
        for (int i = 0; i < 16; i++) d0[tid + i*256] = __ldcg(s0 + tid + i*256);
        #pragma unroll
        for (int i = 0; i < 16; i++) d1[tid + i*256] = __ldcg(s1 + tid + i*256);
    }

    // cell mapping: thread -> (batch pb, unit-pair p); units u0, u0+1
    const int pb = tid >> 2;
    const int p  = tid & 3;
    const int u0 = cb*8 + 2*p;
    const int gbase = pb*HID + u0;

    float2 c_r = *reinterpret_cast<const float2*>(c0 + gbase);
    float2 mh2 = *reinterpret_cast<const float2*>(mh + gbase);
    const int hwaddr = hp_addr(pb, cb*4 + p);

    // bias in registers: bs[i][g] for unit u0+i, gate g
    float bs[2][4];
    #pragma unroll
    for (int i = 0; i < 2; i++)
        #pragma unroll
        for (int g = 0; g < 4; g++)
            bs[i][g] = b_ih[g*HID + u0 + i] + b_hh[g*HID + u0 + i];
    __syncthreads();

    const uint4* wh4 = reinterpret_cast<const uint4*>(sWh);
    const uint4* wi4 = reinterpret_cast<const uint4*>(sWi);

    for (int t = 0; t < SEQ; ++t) {
        float acc[2][4][4];
        #pragma unroll
        for (int mt = 0; mt < 2; mt++)
            #pragma unroll
            for (int nt = 0; nt < 4; nt++)
                #pragma unroll
                for (int e = 0; e < 4; e++) acc[mt][nt][e] = 0.f;

        // ---- x contribution: no dependency on h[t], runs BEFORE the barrier wait ----
        {
            const uint4* xb = reinterpret_cast<const uint4*>(g_xv + (size_t)t*32768);
            MMA_BLOCK(xb, wi4);
        }

        // ---- wait until all CTAs have published h[t] ----
        if (t > 0) {
            if (tid == 0) {
                while (bar_ld_acquire(&g_bar[t-1]) < NCTA) { }
            }
            __syncthreads();
        }

        // ---- h contribution ----
        {
            const uint4* hb = reinterpret_cast<const uint4*>(g_hm[t & 1]);
            MMA_BLOCK(hb, wh4);
        }

        // stage split-K partial gates (proven)
        {
            const int lq = lane >> 2, q4 = lane & 3;
            float* gp = gsm + kq*GSZ;
            #pragma unroll
            for (int mt = 0; mt < 2; mt++) {
                const int r0 = half*32 + mt*16 + lq;
                #pragma unroll
                for (int nt = 0; nt < 4; nt++) {
                    const int c = nt*8 + q4*2;
                    gp[r0*GST + c]       = acc[mt][nt][0];
                    gp[r0*GST + c + 1]   = acc[mt][nt][1];
                    gp[(r0+8)*GST + c]   = acc[mt][nt][2];
                    gp[(r0+8)*GST + c+1] = acc[mt][nt][3];
                }
            }
        }
        __syncthreads();

        // fused LSTM cell
        uint32_t* hmn = g_hm[(t + 1) & 1];
        float hnv[2], cnv[2];
        #pragma unroll
        for (int i = 0; i < 2; i++) {
            const int j = 2*p + i;
            float gt[4];
            #pragma unroll
            for (int g = 0; g < 4; g++) {
                const int c = g*8 + j;
                gt[g] = gsm[0*GSZ + pb*GST + c] + gsm[1*GSZ + pb*GST + c]
                      + gsm[2*GSZ + pb*GST + c] + gsm[3*GSZ + pb*GST + c] + bs[i][g];
            }
            float ig = sigf(gt[0]);
            float fg = sigf(gt[1]);
            float gv = tanh_f(gt[2]);
            float og = sigf(gt[3]);
            float cp = (i == 0) ? c_r.x : c_r.y;
            float cn = fg*cp + ig*gv;
            cnv[i] = cn;
            hnv[i] = og*tanh_f(cn);
        }
        c_r.x = cnv[0]; c_r.y = cnv[1];

        *reinterpret_cast<float2*>(out + (size_t)t*(NB*HID) + gbase)
            = make_float2(hnv[0], hnv[1]);
        hmn[hwaddr] = packh2(hnv[0]*mh2.x, hnv[1]*mh2.y);
        if (t == SEQ - 1) {
            *reinterpret_cast<float2*>(out + SBH + gbase)          = make_float2(hnv[0], hnv[1]);
            *reinterpret_cast<float2*>(out + SBH + NB*HID + gbase) = make_float2(cnv[0], cnv[1]);
        }

        // publish h[t+1]: CTA-wide completion, then release-arrive
        if (t < SEQ - 1) {
            __syncthreads();
            if (tid == 0) bar_red_release(&g_bar[t]);
        }
    }
}

extern "C" void kernel_launch(void* const* d_in, const int* in_sizes, int n_in,
                              void* d_out, int out_size) {
    const float* x      = (const float*)d_in[0];
    const float* h0     = (const float*)d_in[1];
    const float* c0     = (const float*)d_in[2];
    const float* mask_x = (const float*)d_in[3];
    const float* mask_h = (const float*)d_in[4];
    const float* W_ih   = (const float*)d_in[5];
    const float* W_hh   = (const float*)d_in[6];
    const float* b_ih   = (const float*)d_in[7];
    const float* b_hh   = (const float*)d_in[8];
    float* out = (float*)d_out;

    const int smem_rnn = (2*WTILE + 4*GSZ) * 4;   // 131072 + 33792 = 164,864 B
    cudaFuncSetAttribute(k_rnn, cudaFuncAttributeMaxDynamicSharedMemorySize, smem_rnn);

    k_xprep<<<(SEQ*NB*HID/2)/256, 256>>>(x, mask_x);        // 32768 blocks
    k_setup<<<(NB*HID/2)/256, 256>>>(h0, mask_h);           // 128 blocks
    k_wprep<<<(NCTA*WTILE)/256, 256>>>(W_hh, 0);            // 8192 blocks
    k_wprep<<<(NCTA*WTILE)/256, 256>>>(W_ih, 1);            // 8192 blocks
    k_rnn<<<NCTA, 256, smem_rnn>>>(c0, mask_h, b_ih, b_hh, out);
    (void)in_sizes; (void)n_in; (void)out_size;
}

// round 9
// speedup vs baseline: 5.4178x; 1.0735x over previous
#include <cuda_runtime.h>
#include <cuda_fp16.h>
#include <cstdint>

#define SEQ   256
#define NB    64
#define INP   1024
#define HID   1024
#define SBH   (SEQ*NB*HID)
#define NCTA  128
#define GST   33          // gsm row stride (floats)
#define GSZ   (64*GST)    // per-region gate area
#define WTILE 16384       // words per W tile per CTA (32 rows x 1024 k, fp16x2)

// ---- device scratch ----
__device__ uint32_t g_xv[(size_t)SEQ*NB*HID/2];  // x*mask_x, fp16x2, A-frag layout per step
__device__ uint32_t g_hm[2][NB*HID/2];           // masked h, fp16x2, A-frag layout
__device__ uint32_t g_wt[(size_t)2*NCTA*WTILE];  // [0]=W_hh tiles, [1]=W_ih tiles (B-frag)
__device__ int      g_bar[SEQ];                  // grid barrier counters

__device__ __forceinline__ void mma16h(float* d, const uint32_t* a, const uint32_t* b) {
    asm volatile(
        "mma.sync.aligned.m16n8k16.row.col.f32.f16.f16.f32 "
        "{%0,%1,%2,%3},{%4,%5,%6,%7},{%8,%9},{%0,%1,%2,%3};\n"
        : "+f"(d[0]), "+f"(d[1]), "+f"(d[2]), "+f"(d[3])
        : "r"(a[0]), "r"(a[1]), "r"(a[2]), "r"(a[3]), "r"(b[0]), "r"(b[1]));
}
__device__ __forceinline__ float sigf(float x)  { return 1.f/(1.f+__expf(-x)); }
__device__ __forceinline__ float tanh_f(float x){ return 2.f/(1.f+__expf(-2.f*x)) - 1.f; }
__device__ __forceinline__ void bar_red_release(int* p) {
    asm volatile("red.release.gpu.global.add.s32 [%0], 1;" :: "l"(p) : "memory");
}
__device__ __forceinline__ int bar_ld_acquire(int* p) {
    int v;
    asm volatile("ld.acquire.gpu.global.b32 %0, [%1];" : "=r"(v) : "l"(p) : "memory");
    return v;
}
__device__ __forceinline__ uint32_t packh2(float lo, float hi) {
    __half2 h = __floats2half2_rn(lo, hi);   // lo -> low 16 bits (even k)
    return *reinterpret_cast<uint32_t*>(&h);
}
// fp16 A-frag layout: word address for (batch b, k-pair pk); pk = k/2  (proven)
__device__ __forceinline__ int hp_addr(int b, int pk) {
    int mt = b >> 4, rb = b & 15;
    int c  = pk >> 3, pkl = pk & 7;
    int lane = (rb & 7)*4 + (pkl & 3);
    int e    = (pkl >> 2)*2 + (rb >> 3);
    return (mt*64 + c)*128 + lane*4 + e;
}

// ---- x*mask_x -> fp16x2 A-frag layout, per step (proven R8) ----
__global__ void k_xprep(const float* __restrict__ x, const float* __restrict__ mx) {
    int i = blockIdx.x*256 + threadIdx.x;
    int t = i >> 15;
    int d = i & 32767;
    int b = d >> 9, pk = d & 511;
    int u0 = pk*2;
    const float* xs = x  + ((size_t)t*NB + b)*INP + u0;
    const float* ms = mx + (size_t)b*INP + u0;
    g_xv[(size_t)t*32768 + hp_addr(b, pk)] = packh2(xs[0]*ms[0], xs[1]*ms[1]);
}

// ---- init: hm0 = fp16x2(h0*mask_h) in frag layout; zero barriers (proven) ----
__global__ void k_setup(const float* __restrict__ h0, const float* __restrict__ mh) {
    int i = blockIdx.x*256 + threadIdx.x;
    int b = i >> 9, pk = i & 511;
    int u0 = pk*2;
    int s = b*HID + u0;
    g_hm[0][hp_addr(b, pk)] = packh2(h0[s]*mh[s], h0[s+1]*mh[s+1]);
    if (blockIdx.x == 0) g_bar[threadIdx.x] = 0;
}

// ---- W prep: per-CTA fp16x2 tiles in B-fragment layout (proven) ----
__global__ void k_wprep(const float* __restrict__ W, int which) {
    int gi = blockIdx.x*256 + threadIdx.x;
    int cb = gi >> 14;
    int d  = gi & 16383;
    int blk = d >> 7;
    int lane_e = d & 127;
    int chunk = blk >> 1, ntp = blk & 1;
    int lane = lane_e >> 2, e = lane_e & 3;
    int lq = lane >> 2, q4 = lane & 3;
    int nt = ntp*2 + (e >> 1);
    int pk_off = q4 + (e & 1)*4;
    int n = nt*8 + lq;
    int g = n >> 3, j = n & 7;
    const float* src = W + ((size_t)(g*HID + cb*8 + j))*HID + (chunk*8 + pk_off)*2;
    g_wt[(size_t)which*NCTA*WTILE + gi] = packh2(src[0], src[1]);
}

// one per-warp GEMM pass over K=512: whalf = batch half, wkq = K half.
// A-frags from ABASE (uint4, A-frag layout), B from W4 (SMEM uint4).
#define MMA_PASS(ABASE, W4) do {                                               \
    const uint4* ap0 = (ABASE) + whalf*2*2048 + wkq*1024 + lane;               \
    const uint4* ap1 = ap0 + 2048;                                             \
    uint4 afr[8][2];                                                           \
    _Pragma("unroll")                                                          \
    for (int s = 0; s < 8; s++) {                                              \
        afr[s][0] = __ldcg(ap0 + s*32);                                        \
        afr[s][1] = __ldcg(ap1 + s*32);                                        \
    }                                                                          \
    _Pragma("unroll")                                                          \
    for (int g8 = 0; g8 < 4; g8++) {                                           \
        _Pragma("unroll")                                                      \
        for (int s = 0; s < 8; s++) {                                          \
            const int cq = g8*8 + s;                                           \
            uint4 A0 = afr[s][0], A1 = afr[s][1];                              \
            if (g8 < 3) {                                                      \
                afr[s][0] = __ldcg(ap0 + (cq+8)*32);                           \
                afr[s][1] = __ldcg(ap1 + (cq+8)*32);                           \
            }                                                                  \
            const int bidx = (wkq*32 + cq)*64 + lane;                          \
            uint4 b01 = (W4)[bidx];                                            \
            uint4 b23 = (W4)[bidx + 32];                                       \
            uint32_t af0[4] = {A0.x, A0.y, A0.z, A0.w};                        \
            uint32_t af1[4] = {A1.x, A1.y, A1.z, A1.w};                        \
            uint32_t bf0[2] = {b01.x, b01.y};                                  \
            uint32_t bf1[2] = {b01.z, b01.w};                                  \
            uint32_t bf2[2] = {b23.x, b23.y};                                  \
            uint32_t bf3[2] = {b23.z, b23.w};                                  \
            mma16h(acc[0][0], af0, bf0); mma16h(acc[1][0], af1, bf0);          \
            mma16h(acc[0][1], af0, bf1); mma16h(acc[1][1], af1, bf1);          \
            mma16h(acc[0][2], af0, bf2); mma16h(acc[1][2], af1, bf2);          \
            mma16h(acc[0][3], af0, bf3); mma16h(acc[1][3], af1, bf3);          \
        }                                                                      \
    }                                                                          \
} while (0)

// ---- fused persistent LSTM, warp-specialized: warps 0-3 x-GEMM, warps 4-7 h-GEMM ----
__global__ void __launch_bounds__(256, 1) k_rnn(const float* __restrict__ c0,
                                                const float* __restrict__ mh,
                                                const float* __restrict__ b_ih,
                                                const float* __restrict__ b_hh,
                                                float* __restrict__ out) {
    extern __shared__ uint32_t sm[];
    uint32_t* sWh = sm;                    // W_hh tile, 16384 words
    uint32_t* sWi = sm + WTILE;            // W_ih tile, 16384 words
    float*    gsm = (float*)(sm + 2*WTILE);

    const int cb   = blockIdx.x;
    const int tid  = threadIdx.x;
    const int lane = tid & 31;
    const int w    = tid >> 5;
    const bool isx = (w < 4);              // x-GEMM warps
    const int wl   = w & 3;
    const int whalf = wl & 1;              // batch half (32 rows)
    const int wkq   = wl >> 1;             // K half (512 k)

    // preload both W tiles (proven copy pattern)
    {
        const uint4* s0 = reinterpret_cast<const uint4*>(g_wt + (size_t)cb*WTILE);
        const uint4* s1 = reinterpret_cast<const uint4*>(g_wt + (size_t)(NCTA + cb)*WTILE);
        uint4* d0 = reinterpret_cast<uint4*>(sWh);
        uint4* d1 = reinterpret_cast<uint4*>(sWi);
        #pragma unroll
        for (int i = 0; i < 16; i++) d0[tid + i*256] = __ldcg(s0 + tid + i*256);
        #pragma unroll
        for (int i = 0; i < 16; i++) d1[tid + i*256] = __ldcg(s1 + tid + i*256);
    }

    // cell mapping: thread -> (batch pb, unit-pair p); units u0, u0+1
    const int pb = tid >> 2;
    const int p  = tid & 3;
    const int u0 = cb*8 + 2*p;
    const int gbase = pb*HID + u0;

    float2 c_r = *reinterpret_cast<const float2*>(c0 + gbase);
    float2 mh2 = *reinterpret_cast<const float2*>(mh + gbase);
    const int hwaddr = hp_addr(pb, cb*4 + p);

    float bs[2][4];
    #pragma unroll
    for (int i = 0; i < 2; i++)
        #pragma unroll
        for (int g = 0; g < 4; g++)
            bs[i][g] = b_ih[g*HID + u0 + i] + b_hh[g*HID + u0 + i];
    __syncthreads();

    const uint4* wh4 = reinterpret_cast<const uint4*>(sWh);
    const uint4* wi4 = reinterpret_cast<const uint4*>(sWi);

    for (int t = 0; t < SEQ; ++t) {
        float acc[2][4][4];
        #pragma unroll
        for (int mt = 0; mt < 2; mt++)
            #pragma unroll
            for (int nt = 0; nt < 4; nt++)
                #pragma unroll
                for (int e = 0; e < 4; e++) acc[mt][nt][e] = 0.f;

        if (isx) {
            // ---- x contribution: no dependency on h[t] ----
            const uint4* xb = reinterpret_cast<const uint4*>(g_xv + (size_t)t*32768);
            MMA_PASS(xb, wi4);
            float* gp = gsm + wkq*GSZ;          // regions 0,1
            const int lq = lane >> 2, q4 = lane & 3;
            #pragma unroll
            for (int mt = 0; mt < 2; mt++) {
                const int r0 = whalf*32 + mt*16 + lq;
                #pragma unroll
                for (int nt = 0; nt < 4; nt++) {
                    const int c = nt*8 + q4*2;
                    gp[r0*GST + c]       = acc[mt][nt][0];
                    gp[r0*GST + c + 1]   = acc[mt][nt][1];
                    gp[(r0+8)*GST + c]   = acc[mt][nt][2];
                    gp[(r0+8)*GST + c+1] = acc[mt][nt][3];
                }
            }
        } else {
            // ---- h contribution: wait for h[t] first (per-warp poll) ----
            if (t > 0) {
                if (lane == 0) {
                    while (bar_ld_acquire(&g_bar[t-1]) < NCTA) { }
                }
                __syncwarp();
            }
            const uint4* hb = reinterpret_cast<const uint4*>(g_hm[t & 1]);
            MMA_PASS(hb, wh4);
            float* gp = gsm + (2 + wkq)*GSZ;    // regions 2,3
            const int lq = lane >> 2, q4 = lane & 3;
            #pragma unroll
            for (int mt = 0; mt < 2; mt++) {
                const int r0 = whalf*32 + mt*16 + lq;
                #pragma unroll
                for (int nt = 0; nt < 4; nt++) {
                    const int c = nt*8 + q4*2;
                    gp[r0*GST + c]       = acc[mt][nt][0];
                    gp[r0*GST + c + 1]   = acc[mt][nt][1];
                    gp[(r0+8)*GST + c]   = acc[mt][nt][2];
                    gp[(r0+8)*GST + c+1] = acc[mt][nt][3];
                }
            }
        }
        __syncthreads();

        // fused LSTM cell (proven)
        uint32_t* hmn = g_hm[(t + 1) & 1];
        float hnv[2], cnv[2];
        #pragma unroll
        for (int i = 0; i < 2; i++) {
            const int j = 2*p + i;
            float gt[4];
            #pragma unroll
            for (int g = 0; g < 4; g++) {
                const int c = g*8 + j;
                gt[g] = gsm[0*GSZ + pb*GST + c] + gsm[1*GSZ + pb*GST + c]
                      + gsm[2*GSZ + pb*GST + c] + gsm[3*GSZ + pb*GST + c] + bs[i][g];
            }
            float ig = sigf(gt[0]);
            float fg = sigf(gt[1]);
            float gv = tanh_f(gt[2]);
            float og = sigf(gt[3]);
            float cp = (i == 0) ? c_r.x : c_r.y;
            float cn = fg*cp + ig*gv;
            cnv[i] = cn;
            hnv[i] = og*tanh_f(cn);
        }
        c_r.x = cnv[0]; c_r.y = cnv[1];

        *reinterpret_cast<float2*>(out + (size_t)t*(NB*HID) + gbase)
            = make_float2(hnv[0], hnv[1]);
        hmn[hwaddr] = packh2(hnv[0]*mh2.x, hnv[1]*mh2.y);
        if (t == SEQ - 1) {
            *reinterpret_cast<float2*>(out + SBH + gbase)          = make_float2(hnv[0], hnv[1]);
            *reinterpret_cast<float2*>(out + SBH + NB*HID + gbase) = make_float2(cnv[0], cnv[1]);
        }

        // publish h[t+1]: CTA-wide completion, then release-arrive
        if (t < SEQ - 1) {
            __syncthreads();
            if (tid == 0) bar_red_release(&g_bar[t]);
        }
    }
}

extern "C" void kernel_launch(void* const* d_in, const int* in_sizes, int n_in,
                              void* d_out, int out_size) {
    const float* x      = (const float*)d_in[0];
    const float* h0     = (const float*)d_in[1];
    const float* c0     = (const float*)d_in[2];
    const float* mask_x = (const float*)d_in[3];
    const float* mask_h = (const float*)d_in[4];
    const float* W_ih   = (const float*)d_in[5];
    const float* W_hh   = (const float*)d_in[6];
    const float* b_ih   = (const float*)d_in[7];
    const float* b_hh   = (const float*)d_in[8];
    float* out = (float*)d_out;

    const int smem_rnn = (2*WTILE + 4*GSZ) * 4;   // 164,864 B
    cudaFuncSetAttribute(k_rnn, cudaFuncAttributeMaxDynamicSharedMemorySize, smem_rnn);

    k_xprep<<<(SEQ*NB*HID/2)/256, 256>>>(x, mask_x);
    k_setup<<<(NB*HID/2)/256, 256>>>(h0, mask_h);
    k_wprep<<<(NCTA*WTILE)/256, 256>>>(W_hh, 0);
    k_wprep<<<(NCTA*WTILE)/256, 256>>>(W_ih, 1);
    k_rnn<<<NCTA, 256, smem_rnn>>>(c0, mask_h, b_ih, b_hh, out);
    (void)in_sizes; (void)n_in; (void)out_size;
}